// round 5
// baseline (speedup 1.0000x reference)
#include <cuda_runtime.h>

#define N_NODES 30000
#define L_CONT  5
#define K_FAN   16

// ---------------- device scratch (static: no allocations allowed) ----------------
__device__ float g_xg [N_NODES * L_CONT * 512];  // content input-gate precompute (reused a then b)
__device__ float g_Ga [N_NODES * 512];           // neighbor gate table for src type a
__device__ float g_Gb [N_NODES * 512];           // neighbor gate table for src type b
__device__ float g_ca [N_NODES * 128];
__device__ float g_cb [N_NODES * 128];
__device__ float g_naa[N_NODES * 128];
__device__ float g_nba[N_NODES * 128];
__device__ float g_nab[N_NODES * 128];
__device__ float g_nbb[N_NODES * 128];
__device__ float g_wsw[4 * 32768];               // swizzled Whh for ca, cb, na, nb

// ---------------- helpers ----------------
__device__ __forceinline__ float sigf(float x) {
    return __fdividef(1.f, 1.f + __expf(-x));
}
__device__ __forceinline__ float tanh_f(float x) {
    return __fdividef(2.f, 1.f + __expf(-2.f * x)) - 1.f;
}

// ---------------- Whh swizzle: out[p][dir][go][jb][t][jj] = Whh_p[dir][go*64+t][jb*4+jj] ----
__global__ void swz_kernel(const float* __restrict__ w0, const float* __restrict__ w1,
                           const float* __restrict__ w2, const float* __restrict__ w3,
                           float* __restrict__ out)
{
    int i = blockIdx.x * 256 + threadIdx.x;           // 4 * 32768 total
    if (i >= 4 * 32768) return;
    int p  = i >> 15;
    int r  = i & 32767;
    int jj = r & 3;
    int t  = (r >> 2) & 63;
    int jb = (r >> 8) & 15;
    int go = (r >> 12) & 3;
    int d  = (r >> 14) & 1;
    const float* w = (p == 0) ? w0 : (p == 1) ? w1 : (p == 2) ? w2 : w3;
    out[i] = w[d * 16384 + (go * 64 + t) * 64 + jb * 4 + jj];
}

// ---------------- GEMM: C[M,512] = A[M,128] * W[512,128]^T (both k-contiguous) --------------
// block: 256 threads, tile 64 rows x 128 cols, thread 4x8
__global__ void __launch_bounds__(256)
gemm_nt(const float* __restrict__ A, const float* __restrict__ W,
        float* __restrict__ C, int M)
{
    __shared__ float As[64][36];
    __shared__ float Ws[128][36];
    int row0 = blockIdx.x * 64;
    int col0 = blockIdx.y * 128;
    int tid = threadIdx.x;
    int tx = tid & 15;     // col group (8 cols, strided by 16)
    int ty = tid >> 4;     // row group (4 rows)

    float acc[4][8];
#pragma unroll
    for (int r = 0; r < 4; r++)
#pragma unroll
        for (int c = 0; c < 8; c++) acc[r][c] = 0.f;

    for (int kk = 0; kk < 128; kk += 32) {
        // A tile: 64x32 = 512 float4
#pragma unroll
        for (int i = 0; i < 2; i++) {
            int idx4 = tid + i * 256;
            int r = idx4 >> 3;
            int c4 = (idx4 & 7) * 4;
            float4 v = make_float4(0.f, 0.f, 0.f, 0.f);
            int gr = row0 + r;
            if (gr < M) v = *(const float4*)(A + (size_t)gr * 128 + kk + c4);
            *(float4*)(&As[r][c4]) = v;
        }
        // W tile: 128x32 = 1024 float4 (always in-bounds: 512 rows total)
#pragma unroll
        for (int i = 0; i < 4; i++) {
            int idx4 = tid + i * 256;
            int r = idx4 >> 3;
            int c4 = (idx4 & 7) * 4;
            float4 v = *(const float4*)(W + (size_t)(col0 + r) * 128 + kk + c4);
            *(float4*)(&Ws[r][c4]) = v;
        }
        __syncthreads();
#pragma unroll
        for (int k4 = 0; k4 < 32; k4 += 4) {
            float4 a4[4], w4[8];
#pragma unroll
            for (int r = 0; r < 4; r++) a4[r] = *(const float4*)(&As[ty * 4 + r][k4]);
#pragma unroll
            for (int c = 0; c < 8; c++) w4[c] = *(const float4*)(&Ws[tx + 16 * c][k4]);
#pragma unroll
            for (int r = 0; r < 4; r++)
#pragma unroll
                for (int c = 0; c < 8; c++) {
                    acc[r][c] += a4[r].x * w4[c].x;
                    acc[r][c] += a4[r].y * w4[c].y;
                    acc[r][c] += a4[r].z * w4[c].z;
                    acc[r][c] += a4[r].w * w4[c].w;
                }
        }
        __syncthreads();
    }
#pragma unroll
    for (int r = 0; r < 4; r++) {
        int gr = row0 + ty * 4 + r;
        if (gr < M) {
#pragma unroll
            for (int c = 0; c < 8; c++)
                C[(size_t)gr * 512 + col0 + tx + 16 * c] = acc[r][c];
        }
    }
}

// ---------------- fused BiLSTM + mean ----------------
// 512 threads = 8 groups of 64. group gi: dir = gi&1, slot = gi>>1 -> 4 nodes per group-slot,
// 16 nodes per block. Each thread owns hidden unit t for 4 nodes, computes all 4 gates.
// Whh staged in smem pre-swizzled [dir][gate][jb][t][4] for conflict-free LDS.128.
// GATHER=false: Xg rows indexed n*L + seq (content). GATHER=true: rows = idx[n*16+seq] (neighbor).
template<int L, bool GATHER>
__global__ void __launch_bounds__(512, 1)
lstm_kernel(const float* __restrict__ Xg, const int* __restrict__ idx,
            const float* __restrict__ wsw_g, const float* __restrict__ bias,
            float* __restrict__ outp)
{
    extern __shared__ float smem[];
    float* wsw  = smem;                       // 32768 floats (128 KB)
    float* hsm  = smem + 32768;               // 8 groups * 4 nodes * 64 = 2048 floats
    int*   idxs = (int*)(smem + 32768 + 2048);// 256 ints (neighbor only)

    int tid = threadIdx.x;
#pragma unroll
    for (int i = 0; i < 16; i++)
        ((float4*)wsw)[tid + i * 512] = ((const float4*)wsw_g)[tid + i * 512];
    if (GATHER && tid < 256) idxs[tid] = idx[blockIdx.x * 256 + tid];

    int gi = tid >> 6, t = tid & 63;
    int dir = gi & 1, slot = gi >> 1;
    int nbase = blockIdx.x * 16 + slot * 4;

    float b0 = bias[dir * 256 + t];
    float b1 = bias[dir * 256 + 64 + t];
    float b2 = bias[dir * 256 + 128 + t];
    float b3 = bias[dir * 256 + 192 + t];

    const float* wdir = wsw + dir * 16384;   // [4 gates][16 jb][64 t][4]
    float* hrow = hsm + gi * 256;            // [4 nodes][64]

    float cst[4]  = {0.f, 0.f, 0.f, 0.f};
    float hsum[4] = {0.f, 0.f, 0.f, 0.f};
    float xgc[4][4], xgn[4][4];

    __syncthreads();

    // prologue: fetch step-0 input gates
#pragma unroll
    for (int m = 0; m < 4; m++) {
        int seq0 = dir ? (L - 1) : 0;
        int row = GATHER ? idxs[(slot * 4 + m) * L + seq0] : ((nbase + m) * L + seq0);
        const float* p = Xg + (size_t)row * 512 + (dir << 8) + t;
        xgc[m][0] = p[0]; xgc[m][1] = p[64]; xgc[m][2] = p[128]; xgc[m][3] = p[192];
    }

#pragma unroll 1
    for (int l = 0; l < L; l++) {
        // prefetch next step's input gates (hides gather latency behind the matmul)
        if (l + 1 < L) {
            int seq = dir ? (L - 2 - l) : (l + 1);
#pragma unroll
            for (int m = 0; m < 4; m++) {
                int row = GATHER ? idxs[(slot * 4 + m) * L + seq] : ((nbase + m) * L + seq);
                const float* p = Xg + (size_t)row * 512 + (dir << 8) + t;
                xgn[m][0] = p[0]; xgn[m][1] = p[64]; xgn[m][2] = p[128]; xgn[m][3] = p[192];
            }
        }
        float acc[4][4];
#pragma unroll
        for (int m = 0; m < 4; m++) {
            acc[m][0] = xgc[m][0] + b0;
            acc[m][1] = xgc[m][1] + b1;
            acc[m][2] = xgc[m][2] + b2;
            acc[m][3] = xgc[m][3] + b3;
        }
        if (l > 0) {   // step 0 has h = 0
#pragma unroll
            for (int jb = 0; jb < 16; jb++) {
                float4 w0 = *(const float4*)(wdir + ((0 * 16 + jb) * 64 + t) * 4);
                float4 w1 = *(const float4*)(wdir + ((1 * 16 + jb) * 64 + t) * 4);
                float4 w2 = *(const float4*)(wdir + ((2 * 16 + jb) * 64 + t) * 4);
                float4 w3 = *(const float4*)(wdir + ((3 * 16 + jb) * 64 + t) * 4);
#pragma unroll
                for (int m = 0; m < 4; m++) {
                    float4 h4 = *(const float4*)(hrow + m * 64 + jb * 4);
                    acc[m][0] += w0.x * h4.x; acc[m][0] += w0.y * h4.y;
                    acc[m][0] += w0.z * h4.z; acc[m][0] += w0.w * h4.w;
                    acc[m][1] += w1.x * h4.x; acc[m][1] += w1.y * h4.y;
                    acc[m][1] += w1.z * h4.z; acc[m][1] += w1.w * h4.w;
                    acc[m][2] += w2.x * h4.x; acc[m][2] += w2.y * h4.y;
                    acc[m][2] += w2.z * h4.z; acc[m][2] += w2.w * h4.w;
                    acc[m][3] += w3.x * h4.x; acc[m][3] += w3.y * h4.y;
                    acc[m][3] += w3.z * h4.z; acc[m][3] += w3.w * h4.w;
                }
            }
        }
        // group barrier: all reads of old h done before overwrite
        asm volatile("bar.sync %0, 64;" :: "r"(gi + 1) : "memory");
#pragma unroll
        for (int m = 0; m < 4; m++) {
            float ig = sigf(acc[m][0]);
            float fg = sigf(acc[m][1]);
            float gg = tanh_f(acc[m][2]);
            float og = sigf(acc[m][3]);
            cst[m] = fg * cst[m] + ig * gg;
            float h = og * tanh_f(cst[m]);
            hsum[m] += h;
            hrow[m * 64 + t] = h;
        }
        asm volatile("bar.sync %0, 64;" :: "r"(gi + 1) : "memory");
#pragma unroll
        for (int m = 0; m < 4; m++) {
            xgc[m][0] = xgn[m][0]; xgc[m][1] = xgn[m][1];
            xgc[m][2] = xgn[m][2]; xgc[m][3] = xgn[m][3];
        }
    }
    float inv = 1.f / (float)L;
#pragma unroll
    for (int m = 0; m < 4; m++)
        outp[(size_t)(nbase + m) * 128 + dir * 64 + t] = hsum[m] * inv;
}

// ---------------- attention combine: one warp per node ----------------
__global__ void __launch_bounds__(256)
combine_kernel(const float* __restrict__ c, const float* __restrict__ n1,
               const float* __restrict__ n2, const float* __restrict__ attn,
               float* __restrict__ out)
{
    int warp = threadIdx.x >> 5, lane = threadIdx.x & 31;
    int n = blockIdx.x * 8 + warp;
    size_t off = (size_t)n * 128 + lane * 4;
    float4 cv = *(const float4*)(c + off);
    float4 e1 = *(const float4*)(n1 + off);
    float4 e2 = *(const float4*)(n2 + off);
    float4 ac = *(const float4*)(attn + lane * 4);
    float4 ae = *(const float4*)(attn + 128 + lane * 4);

    float base = ac.x * cv.x + ac.y * cv.y + ac.z * cv.z + ac.w * cv.w;
    float d0   = ae.x * cv.x + ae.y * cv.y + ae.z * cv.z + ae.w * cv.w;
    float d1   = ae.x * e1.x + ae.y * e1.y + ae.z * e1.z + ae.w * e1.w;
    float d2   = ae.x * e2.x + ae.y * e2.y + ae.z * e2.z + ae.w * e2.w;
#pragma unroll
    for (int s = 16; s > 0; s >>= 1) {
        base += __shfl_xor_sync(0xffffffffu, base, s);
        d0   += __shfl_xor_sync(0xffffffffu, d0, s);
        d1   += __shfl_xor_sync(0xffffffffu, d1, s);
        d2   += __shfl_xor_sync(0xffffffffu, d2, s);
    }
    float s0 = base + d0, s1 = base + d1, s2 = base + d2;
    s0 = (s0 >= 0.f) ? s0 : 0.01f * s0;   // leaky_relu slope 0.01
    s1 = (s1 >= 0.f) ? s1 : 0.01f * s1;
    s2 = (s2 >= 0.f) ? s2 : 0.01f * s2;
    float mx = fmaxf(s0, fmaxf(s1, s2));
    float w0 = __expf(s0 - mx), w1 = __expf(s1 - mx), w2 = __expf(s2 - mx);
    float inv = __fdividef(1.f, w0 + w1 + w2);
    w0 *= inv; w1 *= inv; w2 *= inv;
    float4 o;
    o.x = w0 * cv.x + w1 * e1.x + w2 * e2.x;
    o.y = w0 * cv.y + w1 * e1.y + w2 * e2.y;
    o.z = w0 * cv.z + w1 * e1.z + w2 * e2.z;
    o.w = w0 * cv.w + w1 * e1.w + w2 * e2.w;
    *(float4*)(out + off) = o;
}

// ---------------- launch ----------------
extern "C" void kernel_launch(void* const* d_in, const int* in_sizes, int n_in,
                              void* d_out, int out_size)
{
    const float* feats_a = (const float*)d_in[0];
    const float* feats_b = (const float*)d_in[1];
    const float* Wih_ca  = (const float*)d_in[2];
    const float* Whh_ca  = (const float*)d_in[3];
    const float* b_ca    = (const float*)d_in[4];
    const float* Wih_cb  = (const float*)d_in[5];
    const float* Whh_cb  = (const float*)d_in[6];
    const float* b_cb    = (const float*)d_in[7];
    const float* Wih_na  = (const float*)d_in[8];
    const float* Whh_na  = (const float*)d_in[9];
    const float* b_na    = (const float*)d_in[10];
    const float* Wih_nb  = (const float*)d_in[11];
    const float* Whh_nb  = (const float*)d_in[12];
    const float* b_nb    = (const float*)d_in[13];
    const float* attn_a  = (const float*)d_in[14];
    const float* attn_b  = (const float*)d_in[15];
    const int* idx_a_a   = (const int*)d_in[16];
    const int* idx_b_a   = (const int*)d_in[17];
    const int* idx_a_b   = (const int*)d_in[18];
    const int* idx_b_b   = (const int*)d_in[19];
    float* out = (float*)d_out;

    float *xg, *Ga, *Gb, *ca, *cb, *naa, *nba, *nab, *nbb, *wsw;
    cudaGetSymbolAddress((void**)&xg,  g_xg);
    cudaGetSymbolAddress((void**)&Ga,  g_Ga);
    cudaGetSymbolAddress((void**)&Gb,  g_Gb);
    cudaGetSymbolAddress((void**)&ca,  g_ca);
    cudaGetSymbolAddress((void**)&cb,  g_cb);
    cudaGetSymbolAddress((void**)&naa, g_naa);
    cudaGetSymbolAddress((void**)&nba, g_nba);
    cudaGetSymbolAddress((void**)&nab, g_nab);
    cudaGetSymbolAddress((void**)&nbb, g_nbb);
    cudaGetSymbolAddress((void**)&wsw, g_wsw);

    const int smem_bytes = 32768 * 4 + 2048 * 4 + 256 * 4;  // 140288
    cudaFuncSetAttribute((const void*)lstm_kernel<L_CONT, false>,
                         cudaFuncAttributeMaxDynamicSharedMemorySize, smem_bytes);
    cudaFuncSetAttribute((const void*)lstm_kernel<K_FAN, true>,
                         cudaFuncAttributeMaxDynamicSharedMemorySize, smem_bytes);

    // 0) swizzle all four Whh param sets
    swz_kernel<<<512, 256>>>(Whh_ca, Whh_cb, Whh_na, Whh_nb, wsw);

    dim3 gemm_big((N_NODES * L_CONT + 63) / 64, 4);   // M = 150000
    dim3 gemm_small((N_NODES + 63) / 64, 4);          // M = 30000

    // 1) content type a: xg GEMM + BiLSTM-mean
    gemm_nt<<<gemm_big, 256>>>(feats_a, Wih_ca, xg, N_NODES * L_CONT);
    lstm_kernel<L_CONT, false><<<N_NODES / 16, 512, smem_bytes>>>(xg, nullptr, wsw + 0, b_ca, ca);

    // 2) content type b (reuses xg buffer; stream-ordered)
    gemm_nt<<<gemm_big, 256>>>(feats_b, Wih_cb, xg, N_NODES * L_CONT);
    lstm_kernel<L_CONT, false><<<N_NODES / 16, 512, smem_bytes>>>(xg, nullptr, wsw + 32768, b_cb, cb);

    // 3) neighbor gate tables: G_src = c_src @ Wih_n^T  (gather commutes with the GEMM)
    gemm_nt<<<gemm_small, 256>>>(ca, Wih_na, Ga, N_NODES);
    gemm_nt<<<gemm_small, 256>>>(cb, Wih_nb, Gb, N_NODES);

    // 4) neighbor BiLSTMs over gathered gate rows
    lstm_kernel<K_FAN, true><<<N_NODES / 16, 512, smem_bytes>>>(Ga, idx_a_a, wsw + 2 * 32768, b_na, naa);
    lstm_kernel<K_FAN, true><<<N_NODES / 16, 512, smem_bytes>>>(Gb, idx_b_a, wsw + 3 * 32768, b_nb, nba);
    lstm_kernel<K_FAN, true><<<N_NODES / 16, 512, smem_bytes>>>(Ga, idx_a_b, wsw + 2 * 32768, b_na, nab);
    lstm_kernel<K_FAN, true><<<N_NODES / 16, 512, smem_bytes>>>(Gb, idx_b_b, wsw + 3 * 32768, b_nb, nbb);

    // 5) attention combine -> out[2, N, 128]
    combine_kernel<<<N_NODES / 8, 256>>>(ca, naa, nba, attn_a, out);
    combine_kernel<<<N_NODES / 8, 256>>>(cb, nab, nbb, attn_b, out + (size_t)N_NODES * 128);
}

// round 7
// speedup vs baseline: 1.1137x; 1.1137x over previous
#include <cuda_runtime.h>
#include <cuda_bf16.h>
#include <cstdint>

#define N_NODES 30000
#define L_CONT  5
#define K_FAN   16
#define CCHUNK  6000          // content chunk (xg chunk = 61.4 MB -> L2 resident)
#define NCHUNK  5

// ---------------- device scratch (static: no allocations allowed) ----------------
__device__ float g_xg [CCHUNK * L_CONT * 512]; // content input-gate chunk buffer
__device__ float g_Ga [N_NODES * 512];         // neighbor gate table for src type a
__device__ float g_Gb [N_NODES * 512];         // neighbor gate table for src type b
__device__ float g_ca [N_NODES * 128];
__device__ float g_cb [N_NODES * 128];
__device__ float g_naa[N_NODES * 128];
__device__ float g_nba[N_NODES * 128];
__device__ float g_nab[N_NODES * 128];
__device__ float g_nbb[N_NODES * 128];
__device__ float g_wsw[4 * 32768];             // swizzled Whh for ca, cb, na, nb

// ---------------- helpers ----------------
__device__ __forceinline__ float sigf(float x) {
    return __fdividef(1.f, 1.f + __expf(-x));
}
__device__ __forceinline__ float tanh_f(float x) {
    return __fdividef(2.f, 1.f + __expf(-2.f * x)) - 1.f;
}

// split two floats into bf16 hi/lo packed pairs
__device__ __forceinline__ void split2(float x, float y, uint32_t& hi, uint32_t& lo) {
    __nv_bfloat16 hx = __float2bfloat16(x);
    __nv_bfloat16 hy = __float2bfloat16(y);
    float rx = x - __bfloat162float(hx);
    float ry = y - __bfloat162float(hy);
    __nv_bfloat162 hv; hv.x = hx; hv.y = hy;
    __nv_bfloat162 lv; lv.x = __float2bfloat16(rx); lv.y = __float2bfloat16(ry);
    hi = *(uint32_t*)&hv;
    lo = *(uint32_t*)&lv;
}

__device__ __forceinline__ void mma_bf16(float* d, const uint32_t* a, uint32_t b0, uint32_t b1) {
    asm volatile(
        "mma.sync.aligned.m16n8k16.row.col.f32.bf16.bf16.f32 "
        "{%0,%1,%2,%3}, {%4,%5,%6,%7}, {%8,%9}, {%0,%1,%2,%3};\n"
        : "+f"(d[0]), "+f"(d[1]), "+f"(d[2]), "+f"(d[3])
        : "r"(a[0]), "r"(a[1]), "r"(a[2]), "r"(a[3]), "r"(b0), "r"(b1));
}

// ---------------- Whh swizzle: out[p][dir][go][jb][t][jj] = Whh_p[dir][go*64+t][jb*4+jj] ----
__global__ void swz_kernel(const float* __restrict__ w0, const float* __restrict__ w1,
                           const float* __restrict__ w2, const float* __restrict__ w3,
                           float* __restrict__ out)
{
    int i = blockIdx.x * 256 + threadIdx.x;           // 4 * 32768 total
    if (i >= 4 * 32768) return;
    int p  = i >> 15;
    int r  = i & 32767;
    int jj = r & 3;
    int t  = (r >> 2) & 63;
    int jb = (r >> 8) & 15;
    int go = (r >> 12) & 3;
    int d  = (r >> 14) & 1;
    const float* w = (p == 0) ? w0 : (p == 1) ? w1 : (p == 2) ? w2 : w3;
    out[i] = w[d * 16384 + (go * 64 + t) * 64 + jb * 4 + jj];
}

// ---------------- tensor-core GEMM: C[M,512] = A[M,128] * W[512,128]^T -----------------
// bf16x3 split (hi*hi + hi*lo + lo*hi), fp32 accumulate -> ~fp32 accuracy.
// 256 threads = 8 warps (4 M x 2 N), block tile 128x128, full K=128 staged in smem.
// smem planes stored as uint32 (2 bf16), row stride 68 words (136 halfs: 8-half pad
// makes the 8-row ldmatrix-style LDS.32 pattern hit all 32 banks).
__global__ void __launch_bounds__(256, 1)
gemm_tc(const float* __restrict__ A, const float* __restrict__ W,
        float* __restrict__ C, int M)
{
    extern __shared__ uint32_t sm[];
    uint32_t* Ahi = sm;
    uint32_t* Alo = sm + 128 * 68;
    uint32_t* Whi = sm + 2 * 128 * 68;
    uint32_t* Wlo = sm + 3 * 128 * 68;

    int tid  = threadIdx.x;
    int row0 = blockIdx.x * 128;
    int col0 = blockIdx.y * 128;

    // ---- stage + split A (128x128 fp32 -> bf16 hi/lo) ----
#pragma unroll
    for (int i = 0; i < 16; i++) {
        int t = tid + i * 256;            // 0..4095
        int r = t >> 5, j = t & 31;       // row, float4 column
        float4 v = make_float4(0.f, 0.f, 0.f, 0.f);
        if (row0 + r < M) v = *(const float4*)(A + (size_t)(row0 + r) * 128 + j * 4);
        uint32_t h0, l0, h1, l1;
        split2(v.x, v.y, h0, l0);
        split2(v.z, v.w, h1, l1);
        Ahi[r * 68 + j * 2]     = h0;
        Ahi[r * 68 + j * 2 + 1] = h1;
        Alo[r * 68 + j * 2]     = l0;
        Alo[r * 68 + j * 2 + 1] = l1;
    }
    // ---- stage + split W tile (rows col0..col0+127, always in-bounds of 512) ----
#pragma unroll
    for (int i = 0; i < 16; i++) {
        int t = tid + i * 256;
        int r = t >> 5, j = t & 31;
        float4 v = *(const float4*)(W + (size_t)(col0 + r) * 128 + j * 4);
        uint32_t h0, l0, h1, l1;
        split2(v.x, v.y, h0, l0);
        split2(v.z, v.w, h1, l1);
        Whi[r * 68 + j * 2]     = h0;
        Whi[r * 68 + j * 2 + 1] = h1;
        Wlo[r * 68 + j * 2]     = l0;
        Wlo[r * 68 + j * 2 + 1] = l1;
    }
    __syncthreads();

    int lane = tid & 31, warp = tid >> 5;
    int wm = warp >> 1, wn = warp & 1;     // 4 x 2 warp grid; warp tile 32 x 64
    int l4 = lane >> 2, lm = lane & 3;

    float acc[2][8][4];
#pragma unroll
    for (int mt = 0; mt < 2; mt++)
#pragma unroll
        for (int nt = 0; nt < 8; nt++)
#pragma unroll
            for (int q = 0; q < 4; q++) acc[mt][nt][q] = 0.f;

#pragma unroll
    for (int ks = 0; ks < 8; ks++) {       // K = 8 x k16
        int kw = ks * 8 + lm;              // word offset within row for this lane
        uint32_t ah[2][4], al[2][4];
#pragma unroll
        for (int mt = 0; mt < 2; mt++) {
            int r = wm * 32 + mt * 16 + l4;
            ah[mt][0] = Ahi[(r)     * 68 + kw];
            ah[mt][1] = Ahi[(r + 8) * 68 + kw];
            ah[mt][2] = Ahi[(r)     * 68 + kw + 4];
            ah[mt][3] = Ahi[(r + 8) * 68 + kw + 4];
            al[mt][0] = Alo[(r)     * 68 + kw];
            al[mt][1] = Alo[(r + 8) * 68 + kw];
            al[mt][2] = Alo[(r)     * 68 + kw + 4];
            al[mt][3] = Alo[(r + 8) * 68 + kw + 4];
        }
#pragma unroll
        for (int nt = 0; nt < 8; nt++) {
            int br = wn * 64 + nt * 8 + l4;
            uint32_t bh0 = Whi[br * 68 + kw], bh1 = Whi[br * 68 + kw + 4];
            uint32_t bl0 = Wlo[br * 68 + kw], bl1 = Wlo[br * 68 + kw + 4];
#pragma unroll
            for (int mt = 0; mt < 2; mt++) {
                mma_bf16(acc[mt][nt], ah[mt], bh0, bh1);
                mma_bf16(acc[mt][nt], ah[mt], bl0, bl1);
                mma_bf16(acc[mt][nt], al[mt], bh0, bh1);
            }
        }
    }

    // ---- epilogue: d0,d1 -> (row, col..col+1); d2,d3 -> (row+8, ...) ----
#pragma unroll
    for (int mt = 0; mt < 2; mt++) {
#pragma unroll
        for (int nt = 0; nt < 8; nt++) {
            int r  = row0 + wm * 32 + mt * 16 + l4;
            int cc = col0 + wn * 64 + nt * 8 + lm * 2;
            if (r < M)
                *(float2*)(C + (size_t)r * 512 + cc)
                    = make_float2(acc[mt][nt][0], acc[mt][nt][1]);
            if (r + 8 < M)
                *(float2*)(C + (size_t)(r + 8) * 512 + cc)
                    = make_float2(acc[mt][nt][2], acc[mt][nt][3]);
        }
    }
}

// ---------------- fused BiLSTM + mean ----------------
// 512 threads = 8 groups of 64. group gi: dir = gi&1, slot = gi>>1 -> 4 nodes per group,
// 16 nodes per block. Thread owns hidden unit t for 4 nodes, computes all 4 gates.
// Whh staged in smem pre-swizzled [dir][gate][jb][t][4] (conflict-free LDS.128).
// Double-buffered h -> ONE named barrier per step.
template<int L, bool GATHER>
__global__ void __launch_bounds__(512, 1)
lstm_kernel(const float* __restrict__ Xg, const int* __restrict__ idx,
            const float* __restrict__ wsw_g, const float* __restrict__ bias,
            float* __restrict__ outp)
{
    extern __shared__ float smem[];
    float* wsw  = smem;                        // 32768 floats (128 KB)
    float* hsm  = smem + 32768;                // 8 groups * 2 bufs * 4 nodes * 64 = 4096
    int*   idxs = (int*)(smem + 32768 + 4096); // 256 ints (neighbor only)

    int tid = threadIdx.x;
#pragma unroll
    for (int i = 0; i < 16; i++)
        ((float4*)wsw)[tid + i * 512] = ((const float4*)wsw_g)[tid + i * 512];
    if (GATHER && tid < 256) idxs[tid] = idx[blockIdx.x * 256 + tid];

    int gi = tid >> 6, t = tid & 63;
    int dir = gi & 1, slot = gi >> 1;
    int nbase = blockIdx.x * 16 + slot * 4;

    float b0 = bias[dir * 256 + t];
    float b1 = bias[dir * 256 + 64 + t];
    float b2 = bias[dir * 256 + 128 + t];
    float b3 = bias[dir * 256 + 192 + t];

    const float* wdir = wsw + dir * 16384;    // [4 gates][16 jb][64 t][4]
    float* hbase = hsm + gi * 512;            // [2][4 nodes][64]

    float cst[4]  = {0.f, 0.f, 0.f, 0.f};
    float hsum[4] = {0.f, 0.f, 0.f, 0.f};
    float xgc[4][4], xgn[4][4];

    __syncthreads();

    // prologue: fetch step-0 input gates
#pragma unroll
    for (int m = 0; m < 4; m++) {
        int seq0 = dir ? (L - 1) : 0;
        int row = GATHER ? idxs[(slot * 4 + m) * L + seq0] : ((nbase + m) * L + seq0);
        const float* p = Xg + (size_t)row * 512 + (dir << 8) + t;
        xgc[m][0] = p[0]; xgc[m][1] = p[64]; xgc[m][2] = p[128]; xgc[m][3] = p[192];
    }

#pragma unroll 1
    for (int l = 0; l < L; l++) {
        // prefetch next step's input gates (hides gather latency behind the matmul)
        if (l + 1 < L) {
            int seq = dir ? (L - 2 - l) : (l + 1);
#pragma unroll
            for (int m = 0; m < 4; m++) {
                int row = GATHER ? idxs[(slot * 4 + m) * L + seq] : ((nbase + m) * L + seq);
                const float* p = Xg + (size_t)row * 512 + (dir << 8) + t;
                xgn[m][0] = p[0]; xgn[m][1] = p[64]; xgn[m][2] = p[128]; xgn[m][3] = p[192];
            }
        }
        float acc[4][4];
#pragma unroll
        for (int m = 0; m < 4; m++) {
            acc[m][0] = xgc[m][0] + b0;
            acc[m][1] = xgc[m][1] + b1;
            acc[m][2] = xgc[m][2] + b2;
            acc[m][3] = xgc[m][3] + b3;
        }
        if (l > 0) {   // step 0 has h = 0
            const float* hprev = hbase + ((l & 1) ^ 1) * 256;
#pragma unroll
            for (int jb = 0; jb < 16; jb++) {
                float4 w0 = *(const float4*)(wdir + ((0 * 16 + jb) * 64 + t) * 4);
                float4 w1 = *(const float4*)(wdir + ((1 * 16 + jb) * 64 + t) * 4);
                float4 w2 = *(const float4*)(wdir + ((2 * 16 + jb) * 64 + t) * 4);
                float4 w3 = *(const float4*)(wdir + ((3 * 16 + jb) * 64 + t) * 4);
#pragma unroll
                for (int m = 0; m < 4; m++) {
                    float4 h4 = *(const float4*)(hprev + m * 64 + jb * 4);
                    acc[m][0] += w0.x * h4.x; acc[m][0] += w0.y * h4.y;
                    acc[m][0] += w0.z * h4.z; acc[m][0] += w0.w * h4.w;
                    acc[m][1] += w1.x * h4.x; acc[m][1] += w1.y * h4.y;
                    acc[m][1] += w1.z * h4.z; acc[m][1] += w1.w * h4.w;
                    acc[m][2] += w2.x * h4.x; acc[m][2] += w2.y * h4.y;
                    acc[m][2] += w2.z * h4.z; acc[m][2] += w2.w * h4.w;
                    acc[m][3] += w3.x * h4.x; acc[m][3] += w3.y * h4.y;
                    acc[m][3] += w3.z * h4.z; acc[m][3] += w3.w * h4.w;
                }
            }
        }
        float* hcur = hbase + (l & 1) * 256;
#pragma unroll
        for (int m = 0; m < 4; m++) {
            float ig = sigf(acc[m][0]);
            float fg = sigf(acc[m][1]);
            float gg = tanh_f(acc[m][2]);
            float og = sigf(acc[m][3]);
            cst[m] = fg * cst[m] + ig * gg;
            float h = og * tanh_f(cst[m]);
            hsum[m] += h;
            hcur[m * 64 + t] = h;
        }
        // single barrier: next step reads hcur; writes of step l+1 target hprev,
        // which no thread can touch until everyone passes this barrier.
        asm volatile("bar.sync %0, 64;" :: "r"(gi + 1) : "memory");
#pragma unroll
        for (int m = 0; m < 4; m++) {
            xgc[m][0] = xgn[m][0]; xgc[m][1] = xgn[m][1];
            xgc[m][2] = xgn[m][2]; xgc[m][3] = xgn[m][3];
        }
    }
    float inv = 1.f / (float)L;
#pragma unroll
    for (int m = 0; m < 4; m++)
        outp[(size_t)(nbase + m) * 128 + dir * 64 + t] = hsum[m] * inv;
}

// ---------------- attention combine: one warp per node ----------------
__global__ void __launch_bounds__(256)
combine_kernel(const float* __restrict__ c, const float* __restrict__ n1,
               const float* __restrict__ n2, const float* __restrict__ attn,
               float* __restrict__ out)
{
    int warp = threadIdx.x >> 5, lane = threadIdx.x & 31;
    int n = blockIdx.x * 8 + warp;
    size_t off = (size_t)n * 128 + lane * 4;
    float4 cv = *(const float4*)(c + off);
    float4 e1 = *(const float4*)(n1 + off);
    float4 e2 = *(const float4*)(n2 + off);
    float4 ac = *(const float4*)(attn + lane * 4);
    float4 ae = *(const float4*)(attn + 128 + lane * 4);

    float base = ac.x * cv.x + ac.y * cv.y + ac.z * cv.z + ac.w * cv.w;
    float d0   = ae.x * cv.x + ae.y * cv.y + ae.z * cv.z + ae.w * cv.w;
    float d1   = ae.x * e1.x + ae.y * e1.y + ae.z * e1.z + ae.w * e1.w;
    float d2   = ae.x * e2.x + ae.y * e2.y + ae.z * e2.z + ae.w * e2.w;
#pragma unroll
    for (int s = 16; s > 0; s >>= 1) {
        base += __shfl_xor_sync(0xffffffffu, base, s);
        d0   += __shfl_xor_sync(0xffffffffu, d0, s);
        d1   += __shfl_xor_sync(0xffffffffu, d1, s);
        d2   += __shfl_xor_sync(0xffffffffu, d2, s);
    }
    float s0 = base + d0, s1 = base + d1, s2 = base + d2;
    s0 = (s0 >= 0.f) ? s0 : 0.01f * s0;   // leaky_relu slope 0.01
    s1 = (s1 >= 0.f) ? s1 : 0.01f * s1;
    s2 = (s2 >= 0.f) ? s2 : 0.01f * s2;
    float mx = fmaxf(s0, fmaxf(s1, s2));
    float w0 = __expf(s0 - mx), w1 = __expf(s1 - mx), w2 = __expf(s2 - mx);
    float inv = __fdividef(1.f, w0 + w1 + w2);
    w0 *= inv; w1 *= inv; w2 *= inv;
    float4 o;
    o.x = w0 * cv.x + w1 * e1.x + w2 * e2.x;
    o.y = w0 * cv.y + w1 * e1.y + w2 * e2.y;
    o.z = w0 * cv.z + w1 * e1.z + w2 * e2.z;
    o.w = w0 * cv.w + w1 * e1.w + w2 * e2.w;
    *(float4*)(out + off) = o;
}

// ---------------- launch ----------------
extern "C" void kernel_launch(void* const* d_in, const int* in_sizes, int n_in,
                              void* d_out, int out_size)
{
    const float* feats_a = (const float*)d_in[0];
    const float* feats_b = (const float*)d_in[1];
    const float* Wih_ca  = (const float*)d_in[2];
    const float* Whh_ca  = (const float*)d_in[3];
    const float* b_ca    = (const float*)d_in[4];
    const float* Wih_cb  = (const float*)d_in[5];
    const float* Whh_cb  = (const float*)d_in[6];
    const float* b_cb    = (const float*)d_in[7];
    const float* Wih_na  = (const float*)d_in[8];
    const float* Whh_na  = (const float*)d_in[9];
    const float* b_na    = (const float*)d_in[10];
    const float* Wih_nb  = (const float*)d_in[11];
    const float* Whh_nb  = (const float*)d_in[12];
    const float* b_nb    = (const float*)d_in[13];
    const float* attn_a  = (const float*)d_in[14];
    const float* attn_b  = (const float*)d_in[15];
    const int* idx_a_a   = (const int*)d_in[16];
    const int* idx_b_a   = (const int*)d_in[17];
    const int* idx_a_b   = (const int*)d_in[18];
    const int* idx_b_b   = (const int*)d_in[19];
    float* out = (float*)d_out;

    float *xg, *Ga, *Gb, *ca, *cb, *naa, *nba, *nab, *nbb, *wsw;
    cudaGetSymbolAddress((void**)&xg,  g_xg);
    cudaGetSymbolAddress((void**)&Ga,  g_Ga);
    cudaGetSymbolAddress((void**)&Gb,  g_Gb);
    cudaGetSymbolAddress((void**)&ca,  g_ca);
    cudaGetSymbolAddress((void**)&cb,  g_cb);
    cudaGetSymbolAddress((void**)&naa, g_naa);
    cudaGetSymbolAddress((void**)&nba, g_nba);
    cudaGetSymbolAddress((void**)&nab, g_nab);
    cudaGetSymbolAddress((void**)&nbb, g_nbb);
    cudaGetSymbolAddress((void**)&wsw, g_wsw);

    const int lstm_smem = 32768 * 4 + 4096 * 4 + 256 * 4;     // 148480
    const int gemm_smem = 4 * 128 * 68 * 4;                    // 139264
    cudaFuncSetAttribute((const void*)lstm_kernel<L_CONT, false>,
                         cudaFuncAttributeMaxDynamicSharedMemorySize, lstm_smem);
    cudaFuncSetAttribute((const void*)lstm_kernel<K_FAN, true>,
                         cudaFuncAttributeMaxDynamicSharedMemorySize, lstm_smem);
    cudaFuncSetAttribute((const void*)gemm_tc,
                         cudaFuncAttributeMaxDynamicSharedMemorySize, gemm_smem);

    // 0) swizzle all four Whh param sets
    swz_kernel<<<512, 256>>>(Whh_ca, Whh_cb, Whh_na, Whh_nb, wsw);

    const int Mg = CCHUNK * L_CONT;                  // 30000 rows per content chunk
    dim3 ggrid((Mg + 127) / 128, 4);                 // also exact for table gemms (M=30000)

    // 1) content type a: chunked so xg stays L2-resident between GEMM and LSTM
    for (int c = 0; c < NCHUNK; c++) {
        gemm_tc<<<ggrid, 256, gemm_smem>>>(feats_a + (size_t)c * CCHUNK * L_CONT * 128,
                                           Wih_ca, xg, Mg);
        lstm_kernel<L_CONT, false><<<CCHUNK / 16, 512, lstm_smem>>>(
            xg, nullptr, wsw + 0, b_ca, ca + (size_t)c * CCHUNK * 128);
    }
    // 2) content type b
    for (int c = 0; c < NCHUNK; c++) {
        gemm_tc<<<ggrid, 256, gemm_smem>>>(feats_b + (size_t)c * CCHUNK * L_CONT * 128,
                                           Wih_cb, xg, Mg);
        lstm_kernel<L_CONT, false><<<CCHUNK / 16, 512, lstm_smem>>>(
            xg, nullptr, wsw + 32768, b_cb, cb + (size_t)c * CCHUNK * 128);
    }

    // 3) neighbor gate tables: G_src = c_src @ Wih_n^T  (gather commutes with the GEMM)
    gemm_tc<<<ggrid, 256, gemm_smem>>>(ca, Wih_na, Ga, N_NODES);
    gemm_tc<<<ggrid, 256, gemm_smem>>>(cb, Wih_nb, Gb, N_NODES);

    // 4) neighbor BiLSTMs over gathered gate rows
    lstm_kernel<K_FAN, true><<<N_NODES / 16, 512, lstm_smem>>>(Ga, idx_a_a, wsw + 2 * 32768, b_na, naa);
    lstm_kernel<K_FAN, true><<<N_NODES / 16, 512, lstm_smem>>>(Gb, idx_b_a, wsw + 3 * 32768, b_nb, nba);
    lstm_kernel<K_FAN, true><<<N_NODES / 16, 512, lstm_smem>>>(Ga, idx_a_b, wsw + 2 * 32768, b_na, nab);
    lstm_kernel<K_FAN, true><<<N_NODES / 16, 512, lstm_smem>>>(Gb, idx_b_b, wsw + 3 * 32768, b_nb, nbb);

    // 5) attention combine -> out[2, N, 128]
    combine_kernel<<<N_NODES / 8, 256>>>(ca, naa, nba, attn_a, out);
    combine_kernel<<<N_NODES / 8, 256>>>(cb, nab, nbb, attn_b, out + (size_t)N_NODES * 128);
}

// round 8
// speedup vs baseline: 1.4045x; 1.2612x over previous
#include <cuda_runtime.h>
#include <cuda_bf16.h>
#include <cstdint>

#define N_NODES 30000
#define L_CONT  5
#define K_FAN   16
#define CCHUNK  6000          // content chunk (xg chunk = 61.4 MB -> L2 resident)
#define NCHUNK  5

// ---------------- device scratch (static: no allocations allowed) ----------------
__device__ float    g_xg [CCHUNK * L_CONT * 512]; // content input-gate chunk buffer (swizzled+bias)
__device__ float    g_Ga [N_NODES * 512];         // neighbor gate table, src type a (swizzled+bias)
__device__ float    g_Gb [N_NODES * 512];         // neighbor gate table, src type b
__device__ float    g_ca [N_NODES * 128];
__device__ float    g_cb [N_NODES * 128];
__device__ float    g_naa[N_NODES * 128];
__device__ float    g_nba[N_NODES * 128];
__device__ float    g_nab[N_NODES * 128];
__device__ float    g_nbb[N_NODES * 128];
__device__ uint32_t g_wfrag[4 * 32768];           // Whh B-fragments: [p][dir][split][kt][nt][lane][2]

// ---------------- helpers ----------------
__device__ __forceinline__ float sigf(float x) {
    return __fdividef(1.f, 1.f + __expf(-x));
}
__device__ __forceinline__ float tanh_f(float x) {
    return __fdividef(2.f, 1.f + __expf(-2.f * x)) - 1.f;
}
__device__ __forceinline__ uint32_t packbf(__nv_bfloat16 a, __nv_bfloat16 b) {
    __nv_bfloat162 v; v.x = a; v.y = b;
    return *(uint32_t*)&v;
}
// split two floats into bf16 hi/lo packed pairs
__device__ __forceinline__ void split2(float x, float y, uint32_t& hi, uint32_t& lo) {
    __nv_bfloat16 hx = __float2bfloat16(x);
    __nv_bfloat16 hy = __float2bfloat16(y);
    hi = packbf(hx, hy);
    lo = packbf(__float2bfloat16(x - __bfloat162float(hx)),
                __float2bfloat16(y - __bfloat162float(hy)));
}
__device__ __forceinline__ void mma_bf16(float* d, const uint32_t* a, uint32_t b0, uint32_t b1) {
    asm volatile(
        "mma.sync.aligned.m16n8k16.row.col.f32.bf16.bf16.f32 "
        "{%0,%1,%2,%3}, {%4,%5,%6,%7}, {%8,%9}, {%0,%1,%2,%3};\n"
        : "+f"(d[0]), "+f"(d[1]), "+f"(d[2]), "+f"(d[3])
        : "r"(a[0]), "r"(a[1]), "r"(a[2]), "r"(a[3]), "r"(b0), "r"(b1));
}

// -------- Whh -> B-fragment swizzle (bf16 hi/lo), exact mma.m16n8k16 B layout --------
// out[p][dir][split][kt][nt][lane][j]: n = nt*8 + (lane>>2), k = kt*16 + (lane&3)*2 + j*8
// value = pack(bf16split(Whh[dir][n][k]), bf16split(Whh[dir][n][k+1]))
__global__ void wfrag_kernel(const float* __restrict__ w0, const float* __restrict__ w1,
                             const float* __restrict__ w2, const float* __restrict__ w3,
                             uint32_t* __restrict__ out)
{
    int i = blockIdx.x * 256 + threadIdx.x;          // 131072 total
    int j    = i & 1;
    int lane = (i >> 1) & 31;
    int nt   = (i >> 6) & 31;
    int kt   = (i >> 11) & 3;
    int sp   = (i >> 13) & 1;
    int dir  = (i >> 14) & 1;
    int p    = i >> 15;
    const float* w = (p == 0) ? w0 : (p == 1) ? w1 : (p == 2) ? w2 : w3;
    int n = nt * 8 + (lane >> 2);
    int k = kt * 16 + (lane & 3) * 2 + j * 8;
    float x0 = w[dir * 16384 + n * 64 + k];
    float x1 = w[dir * 16384 + n * 64 + k + 1];
    __nv_bfloat16 h0 = __float2bfloat16(x0);
    __nv_bfloat16 h1 = __float2bfloat16(x1);
    if (sp == 0) out[i] = packbf(h0, h1);
    else out[i] = packbf(__float2bfloat16(x0 - __bfloat162float(h0)),
                         __float2bfloat16(x1 - __bfloat162float(h1)));
}

// ---------------- tensor-core GEMM: C[M,512] = A[M,128] * W[512,128]^T + bias ----------
// bf16x3 split, fp32 accumulate. Epilogue writes gates in the fragment-friendly
// permuted layout: phys(c) = d*256 + lm*64 + nt*2 + b  (d=c>>8, cd=c&255, nt=cd>>3,
// lm=(cd>>1)&3, b=cd&1), and folds in bias[c].
__global__ void __launch_bounds__(256, 1)
gemm_tc(const float* __restrict__ A, const float* __restrict__ W,
        const float* __restrict__ bias, float* __restrict__ C, int M)
{
    extern __shared__ uint32_t sm[];
    uint32_t* Ahi = sm;
    uint32_t* Alo = sm + 128 * 68;
    uint32_t* Whi = sm + 2 * 128 * 68;
    uint32_t* Wlo = sm + 3 * 128 * 68;

    int tid  = threadIdx.x;
    int row0 = blockIdx.x * 128;
    int col0 = blockIdx.y * 128;

#pragma unroll
    for (int i = 0; i < 16; i++) {
        int t = tid + i * 256;
        int r = t >> 5, j = t & 31;
        float4 v = make_float4(0.f, 0.f, 0.f, 0.f);
        if (row0 + r < M) v = *(const float4*)(A + (size_t)(row0 + r) * 128 + j * 4);
        uint32_t h0, l0, h1, l1;
        split2(v.x, v.y, h0, l0);
        split2(v.z, v.w, h1, l1);
        Ahi[r * 68 + j * 2]     = h0;
        Ahi[r * 68 + j * 2 + 1] = h1;
        Alo[r * 68 + j * 2]     = l0;
        Alo[r * 68 + j * 2 + 1] = l1;
    }
#pragma unroll
    for (int i = 0; i < 16; i++) {
        int t = tid + i * 256;
        int r = t >> 5, j = t & 31;
        float4 v = *(const float4*)(W + (size_t)(col0 + r) * 128 + j * 4);
        uint32_t h0, l0, h1, l1;
        split2(v.x, v.y, h0, l0);
        split2(v.z, v.w, h1, l1);
        Whi[r * 68 + j * 2]     = h0;
        Whi[r * 68 + j * 2 + 1] = h1;
        Wlo[r * 68 + j * 2]     = l0;
        Wlo[r * 68 + j * 2 + 1] = l1;
    }
    __syncthreads();

    int lane = tid & 31, warp = tid >> 5;
    int wm = warp >> 1, wn = warp & 1;
    int l4 = lane >> 2, lm = lane & 3;

    float acc[2][8][4];
#pragma unroll
    for (int mt = 0; mt < 2; mt++)
#pragma unroll
        for (int nt = 0; nt < 8; nt++)
#pragma unroll
            for (int q = 0; q < 4; q++) acc[mt][nt][q] = 0.f;

#pragma unroll
    for (int ks = 0; ks < 8; ks++) {
        int kw = ks * 8 + lm;
        uint32_t ah[2][4], al[2][4];
#pragma unroll
        for (int mt = 0; mt < 2; mt++) {
            int r = wm * 32 + mt * 16 + l4;
            ah[mt][0] = Ahi[(r)     * 68 + kw];
            ah[mt][1] = Ahi[(r + 8) * 68 + kw];
            ah[mt][2] = Ahi[(r)     * 68 + kw + 4];
            ah[mt][3] = Ahi[(r + 8) * 68 + kw + 4];
            al[mt][0] = Alo[(r)     * 68 + kw];
            al[mt][1] = Alo[(r + 8) * 68 + kw];
            al[mt][2] = Alo[(r)     * 68 + kw + 4];
            al[mt][3] = Alo[(r + 8) * 68 + kw + 4];
        }
#pragma unroll
        for (int nt = 0; nt < 8; nt++) {
            int br = wn * 64 + nt * 8 + l4;
            uint32_t bh0 = Whi[br * 68 + kw], bh1 = Whi[br * 68 + kw + 4];
            uint32_t bl0 = Wlo[br * 68 + kw], bl1 = Wlo[br * 68 + kw + 4];
#pragma unroll
            for (int mt = 0; mt < 2; mt++) {
                mma_bf16(acc[mt][nt], ah[mt], bh0, bh1);
                mma_bf16(acc[mt][nt], ah[mt], bl0, bl1);
                mma_bf16(acc[mt][nt], al[mt], bh0, bh1);
            }
        }
    }

    // epilogue: permuted layout + bias
#pragma unroll
    for (int mt = 0; mt < 2; mt++) {
#pragma unroll
        for (int nt = 0; nt < 8; nt++) {
            int c  = col0 + wn * 64 + nt * 8 + lm * 2;     // logical col (even)
            int d  = c >> 8, cd = c & 255;
            int pc = d * 256 + ((cd >> 1) & 3) * 64 + (cd >> 3) * 2;
            float b0 = bias[c], b1 = bias[c + 1];
            int r = row0 + wm * 32 + mt * 16 + l4;
            if (r < M)
                *(float2*)(C + (size_t)r * 512 + pc)
                    = make_float2(acc[mt][nt][0] + b0, acc[mt][nt][1] + b1);
            if (r + 8 < M)
                *(float2*)(C + (size_t)(r + 8) * 512 + pc)
                    = make_float2(acc[mt][nt][2] + b0, acc[mt][nt][3] + b1);
        }
    }
}

// ---------------- tensor-core BiLSTM + mean ----------------
// 256 threads = 8 warps. Warp w: dir = w&1, mtile = w>>2? no: mtile = w>>1 (0..3).
// Each warp owns 16 (node,dir) rows and computes the FULL G[16,256] = H @ Whh^T via
// mma.m16n8k16 bf16x3 (hi*hi + hi*lo + lo*hi). Elementwise gates are lane-local;
// h D-fragments repack directly into next step's A-fragments (register-only, no syncs).
// Xg rows are read in the permuted layout written by gemm_tc.
template<int L, bool GATHER>
__global__ void __launch_bounds__(256, 1)
lstm_tc(const float* __restrict__ Xg, const int* __restrict__ idx,
        const uint32_t* __restrict__ wfrag, float* __restrict__ outp, int nnodes)
{
    extern __shared__ uint32_t bsm[];            // 32768: [dir][split][kt][nt][lane][2]
    int* idxs = (int*)(bsm + 32768);             // 64*L ints (neighbor only)

    int tid = threadIdx.x;
#pragma unroll
    for (int i = 0; i < 32; i++)
        ((uint4*)bsm)[tid + i * 256] = ((const uint4*)wfrag)[tid + i * 256];
    if (GATHER) {
        for (int i = tid; i < 64 * L; i += 256) {
            int gix = blockIdx.x * 64 * L + i;
            idxs[i] = (gix < nnodes * L) ? idx[gix] : 0;
        }
    }
    __syncthreads();

    int lane = tid & 31, warp = tid >> 5;
    int dir = warp & 1, mtile = warp >> 1;
    int gr = lane >> 2, lm = lane & 3;
    int lrow0 = mtile * 16 + gr;                 // block-local row 0..63
    int gnode0 = blockIdx.x * 64 + lrow0;
    bool ok0 = gnode0 < nnodes;
    bool ok1 = gnode0 + 8 < nnodes;
    int cn0 = ok0 ? gnode0 : 0;                  // clamped for safe loads
    int cn1 = ok1 ? gnode0 + 8 : 0;

    float acc[32][4];
    float cst[32], hsum[32];
#pragma unroll
    for (int q = 0; q < 32; q++) { cst[q] = 0.f; hsum[q] = 0.f; }
    uint32_t ahi[16], alo[16];

    const uint32_t* bd  = bsm + dir * 16384;     // hi split
    const uint32_t* bdl = bd + 8192;             // lo split

#pragma unroll 1
    for (int l = 0; l < L; l++) {
        int seq = dir ? (L - 1 - l) : l;
        int xr0, xr1;
        if (GATHER) {
            xr0 = ok0 ? idxs[lrow0 * L + seq] : 0;
            xr1 = ok1 ? idxs[(lrow0 + 8) * L + seq] : 0;
        } else {
            xr0 = cn0 * L + seq;
            xr1 = cn1 * L + seq;
        }
        // acc init = Xg (permuted layout, bias already folded in)
        const float* xp0 = Xg + (size_t)xr0 * 512 + (dir << 8) + lm * 64;
        const float* xp1 = Xg + (size_t)xr1 * 512 + (dir << 8) + lm * 64;
#pragma unroll
        for (int pr = 0; pr < 16; pr++) {
            float4 v0 = *(const float4*)(xp0 + pr * 4);
            float4 v1 = *(const float4*)(xp1 + pr * 4);
            acc[2 * pr][0] = v0.x; acc[2 * pr][1] = v0.y;
            acc[2 * pr + 1][0] = v0.z; acc[2 * pr + 1][1] = v0.w;
            acc[2 * pr][2] = v1.x; acc[2 * pr][3] = v1.y;
            acc[2 * pr + 1][2] = v1.z; acc[2 * pr + 1][3] = v1.w;
        }
        if (l > 0) {
#pragma unroll
            for (int kt = 0; kt < 4; kt++) {
                const uint32_t* bk = bd  + kt * 2048 + lane * 2;
                const uint32_t* bl = bdl + kt * 2048 + lane * 2;
#pragma unroll
                for (int nt = 0; nt < 32; nt++) {
                    uint2 bh = *(const uint2*)(bk + nt * 64);
                    uint2 bo = *(const uint2*)(bl + nt * 64);
                    mma_bf16(acc[nt], ahi + kt * 4, bh.x, bh.y);
                    mma_bf16(acc[nt], ahi + kt * 4, bo.x, bo.y);
                    mma_bf16(acc[nt], alo + kt * 4, bh.x, bh.y);
                }
            }
        }
        // elementwise gates (lane-local across i/f/g/o tiles) + D->A repack
#pragma unroll
        for (int q = 0; q < 8; q++) {
            float h[4];
#pragma unroll
            for (int j = 0; j < 4; j++) {
                float ig = sigf(acc[q][j]);
                float fg = sigf(acc[8 + q][j]);
                float gg = tanh_f(acc[16 + q][j]);
                float og = sigf(acc[24 + q][j]);
                float c = fg * cst[q * 4 + j] + ig * gg;
                cst[q * 4 + j] = c;
                float hv = og * tanh_f(c);
                hsum[q * 4 + j] += hv;
                h[j] = hv;
            }
            int kt = q >> 1;
            int hf = (q & 1) * 2;
            __nv_bfloat16 b0 = __float2bfloat16(h[0]);
            __nv_bfloat16 b1 = __float2bfloat16(h[1]);
            __nv_bfloat16 b2 = __float2bfloat16(h[2]);
            __nv_bfloat16 b3 = __float2bfloat16(h[3]);
            ahi[kt * 4 + hf]     = packbf(b0, b1);
            ahi[kt * 4 + hf + 1] = packbf(b2, b3);
            alo[kt * 4 + hf]     = packbf(__float2bfloat16(h[0] - __bfloat162float(b0)),
                                          __float2bfloat16(h[1] - __bfloat162float(b1)));
            alo[kt * 4 + hf + 1] = packbf(__float2bfloat16(h[2] - __bfloat162float(b2)),
                                          __float2bfloat16(h[3] - __bfloat162float(b3)));
        }
    }

    float invL = 1.f / (float)L;
#pragma unroll
    for (int q = 0; q < 8; q++) {
        size_t col = dir * 64 + q * 8 + lm * 2;
        if (ok0)
            *(float2*)(outp + (size_t)gnode0 * 128 + col)
                = make_float2(hsum[q * 4] * invL, hsum[q * 4 + 1] * invL);
        if (ok1)
            *(float2*)(outp + (size_t)(gnode0 + 8) * 128 + col)
                = make_float2(hsum[q * 4 + 2] * invL, hsum[q * 4 + 3] * invL);
    }
}

// ---------------- attention combine: one warp per node ----------------
__global__ void __launch_bounds__(256)
combine_kernel(const float* __restrict__ c, const float* __restrict__ n1,
               const float* __restrict__ n2, const float* __restrict__ attn,
               float* __restrict__ out)
{
    int warp = threadIdx.x >> 5, lane = threadIdx.x & 31;
    int n = blockIdx.x * 8 + warp;
    size_t off = (size_t)n * 128 + lane * 4;
    float4 cv = *(const float4*)(c + off);
    float4 e1 = *(const float4*)(n1 + off);
    float4 e2 = *(const float4*)(n2 + off);
    float4 ac = *(const float4*)(attn + lane * 4);
    float4 ae = *(const float4*)(attn + 128 + lane * 4);

    float base = ac.x * cv.x + ac.y * cv.y + ac.z * cv.z + ac.w * cv.w;
    float d0   = ae.x * cv.x + ae.y * cv.y + ae.z * cv.z + ae.w * cv.w;
    float d1   = ae.x * e1.x + ae.y * e1.y + ae.z * e1.z + ae.w * e1.w;
    float d2   = ae.x * e2.x + ae.y * e2.y + ae.z * e2.z + ae.w * e2.w;
#pragma unroll
    for (int s = 16; s > 0; s >>= 1) {
        base += __shfl_xor_sync(0xffffffffu, base, s);
        d0   += __shfl_xor_sync(0xffffffffu, d0, s);
        d1   += __shfl_xor_sync(0xffffffffu, d1, s);
        d2   += __shfl_xor_sync(0xffffffffu, d2, s);
    }
    float s0 = base + d0, s1 = base + d1, s2 = base + d2;
    s0 = (s0 >= 0.f) ? s0 : 0.01f * s0;
    s1 = (s1 >= 0.f) ? s1 : 0.01f * s1;
    s2 = (s2 >= 0.f) ? s2 : 0.01f * s2;
    float mx = fmaxf(s0, fmaxf(s1, s2));
    float w0 = __expf(s0 - mx), w1 = __expf(s1 - mx), w2 = __expf(s2 - mx);
    float inv = __fdividef(1.f, w0 + w1 + w2);
    w0 *= inv; w1 *= inv; w2 *= inv;
    float4 o;
    o.x = w0 * cv.x + w1 * e1.x + w2 * e2.x;
    o.y = w0 * cv.y + w1 * e1.y + w2 * e2.y;
    o.z = w0 * cv.z + w1 * e1.z + w2 * e2.z;
    o.w = w0 * cv.w + w1 * e1.w + w2 * e2.w;
    *(float4*)(out + off) = o;
}

// ---------------- launch ----------------
extern "C" void kernel_launch(void* const* d_in, const int* in_sizes, int n_in,
                              void* d_out, int out_size)
{
    const float* feats_a = (const float*)d_in[0];
    const float* feats_b = (const float*)d_in[1];
    const float* Wih_ca  = (const float*)d_in[2];
    const float* Whh_ca  = (const float*)d_in[3];
    const float* b_ca    = (const float*)d_in[4];
    const float* Wih_cb  = (const float*)d_in[5];
    const float* Whh_cb  = (const float*)d_in[6];
    const float* b_cb    = (const float*)d_in[7];
    const float* Wih_na  = (const float*)d_in[8];
    const float* Whh_na  = (const float*)d_in[9];
    const float* b_na    = (const float*)d_in[10];
    const float* Wih_nb  = (const float*)d_in[11];
    const float* Whh_nb  = (const float*)d_in[12];
    const float* b_nb    = (const float*)d_in[13];
    const float* attn_a  = (const float*)d_in[14];
    const float* attn_b  = (const float*)d_in[15];
    const int* idx_a_a   = (const int*)d_in[16];
    const int* idx_b_a   = (const int*)d_in[17];
    const int* idx_a_b   = (const int*)d_in[18];
    const int* idx_b_b   = (const int*)d_in[19];
    float* out = (float*)d_out;

    float *xg, *Ga, *Gb, *ca, *cb, *naa, *nba, *nab, *nbb;
    uint32_t* wfrag;
    cudaGetSymbolAddress((void**)&xg,  g_xg);
    cudaGetSymbolAddress((void**)&Ga,  g_Ga);
    cudaGetSymbolAddress((void**)&Gb,  g_Gb);
    cudaGetSymbolAddress((void**)&ca,  g_ca);
    cudaGetSymbolAddress((void**)&cb,  g_cb);
    cudaGetSymbolAddress((void**)&naa, g_naa);
    cudaGetSymbolAddress((void**)&nba, g_nba);
    cudaGetSymbolAddress((void**)&nab, g_nab);
    cudaGetSymbolAddress((void**)&nbb, g_nbb);
    cudaGetSymbolAddress((void**)&wfrag, g_wfrag);

    const int gemm_smem = 4 * 128 * 68 * 4;                 // 139264
    const int lstm_c_smem = 32768 * 4 + 64 * L_CONT * 4;    // 132352
    const int lstm_n_smem = 32768 * 4 + 64 * K_FAN * 4;     // 135168
    cudaFuncSetAttribute((const void*)gemm_tc,
                         cudaFuncAttributeMaxDynamicSharedMemorySize, gemm_smem);
    cudaFuncSetAttribute((const void*)lstm_tc<L_CONT, false>,
                         cudaFuncAttributeMaxDynamicSharedMemorySize, lstm_c_smem);
    cudaFuncSetAttribute((const void*)lstm_tc<K_FAN, true>,
                         cudaFuncAttributeMaxDynamicSharedMemorySize, lstm_n_smem);

    // 0) Whh -> mma B-fragments (bf16 hi/lo), all four param sets
    wfrag_kernel<<<512, 256>>>(Whh_ca, Whh_cb, Whh_na, Whh_nb, wfrag);

    dim3 ggrid((30000 + 127) / 128, 4);        // M=30000 rows per GEMM launch
    const int cblk = (CCHUNK + 63) / 64;       // 94 LSTM blocks per content chunk
    const int nblk = (N_NODES + 63) / 64;      // 469 LSTM blocks per neighbor launch

    // 1) content type a: chunked so xg stays L2-resident between GEMM and LSTM
    for (int c = 0; c < NCHUNK; c++) {
        gemm_tc<<<ggrid, 256, gemm_smem>>>(feats_a + (size_t)c * CCHUNK * L_CONT * 128,
                                           Wih_ca, b_ca, xg, CCHUNK * L_CONT);
        lstm_tc<L_CONT, false><<<cblk, 256, lstm_c_smem>>>(
            xg, nullptr, wfrag + 0 * 32768, ca + (size_t)c * CCHUNK * 128, CCHUNK);
    }
    // 2) content type b
    for (int c = 0; c < NCHUNK; c++) {
        gemm_tc<<<ggrid, 256, gemm_smem>>>(feats_b + (size_t)c * CCHUNK * L_CONT * 128,
                                           Wih_cb, b_cb, xg, CCHUNK * L_CONT);
        lstm_tc<L_CONT, false><<<cblk, 256, lstm_c_smem>>>(
            xg, nullptr, wfrag + 1 * 32768, cb + (size_t)c * CCHUNK * 128, CCHUNK);
    }

    // 3) neighbor gate tables: G_src = c_src @ Wih_n^T + b_n (gather commutes with GEMM)
    gemm_tc<<<ggrid, 256, gemm_smem>>>(ca, Wih_na, b_na, Ga, N_NODES);
    gemm_tc<<<ggrid, 256, gemm_smem>>>(cb, Wih_nb, b_nb, Gb, N_NODES);

    // 4) neighbor BiLSTMs over gathered gate rows (tensor-core recurrence)
    lstm_tc<K_FAN, true><<<nblk, 256, lstm_n_smem>>>(Ga, idx_a_a, wfrag + 2 * 32768, naa, N_NODES);
    lstm_tc<K_FAN, true><<<nblk, 256, lstm_n_smem>>>(Gb, idx_b_a, wfrag + 3 * 32768, nba, N_NODES);
    lstm_tc<K_FAN, true><<<nblk, 256, lstm_n_smem>>>(Ga, idx_a_b, wfrag + 2 * 32768, nab, N_NODES);
    lstm_tc<K_FAN, true><<<nblk, 256, lstm_n_smem>>>(Gb, idx_b_b, wfrag + 3 * 32768, nbb, N_NODES);

    // 5) attention combine -> out[2, N, 128]
    combine_kernel<<<N_NODES / 8, 256>>>(ca, naa, nba, attn_a, out);
    combine_kernel<<<N_NODES / 8, 256>>>(cb, nab, nbb, attn_b, out + (size_t)N_NODES * 128);
}

// round 10
// speedup vs baseline: 1.8569x; 1.3221x over previous
#include <cuda_runtime.h>
#include <cuda_bf16.h>
#include <cstdint>

#define N_NODES 30000
#define L_CONT  5
#define K_FAN   16
#define CCHUNK  6000          // content chunk (xg chunk = 61.4 MB -> L2 resident)
#define NCHUNK  5

// ---------------- device scratch (static: no allocations allowed) ----------------
__device__ float    g_xg [CCHUNK * L_CONT * 512]; // content input-gate chunk buffer (permuted+bias)
__device__ float    g_Ga [N_NODES * 512];         // neighbor gate table, src type a (permuted+bias)
__device__ float    g_Gb [N_NODES * 512];         // neighbor gate table, src type b
__device__ float    g_ca [N_NODES * 128];
__device__ float    g_cb [N_NODES * 128];
__device__ float    g_naa[N_NODES * 128];
__device__ float    g_nba[N_NODES * 128];
__device__ float    g_nab[N_NODES * 128];
__device__ float    g_nbb[N_NODES * 128];
__device__ uint32_t g_wfrag[4 * 32768];           // Whh B-fragments: [p][dir][split][kt][nt][lane][2]

// ---------------- helpers ----------------
__device__ __forceinline__ float sigf(float x) {
    return __fdividef(1.f, 1.f + __expf(-x));
}
__device__ __forceinline__ float tanh_f(float x) {
    return __fdividef(2.f, 1.f + __expf(-2.f * x)) - 1.f;
}
__device__ __forceinline__ uint32_t packbf(__nv_bfloat16 a, __nv_bfloat16 b) {
    __nv_bfloat162 v; v.x = a; v.y = b;
    return *(uint32_t*)&v;
}
__device__ __forceinline__ void split2(float x, float y, uint32_t& hi, uint32_t& lo) {
    __nv_bfloat16 hx = __float2bfloat16(x);
    __nv_bfloat16 hy = __float2bfloat16(y);
    hi = packbf(hx, hy);
    lo = packbf(__float2bfloat16(x - __bfloat162float(hx)),
                __float2bfloat16(y - __bfloat162float(hy)));
}
__device__ __forceinline__ void mma_bf16(float* d, const uint32_t* a, uint32_t b0, uint32_t b1) {
    asm volatile(
        "mma.sync.aligned.m16n8k16.row.col.f32.bf16.bf16.f32 "
        "{%0,%1,%2,%3}, {%4,%5,%6,%7}, {%8,%9}, {%0,%1,%2,%3};\n"
        : "+f"(d[0]), "+f"(d[1]), "+f"(d[2]), "+f"(d[3])
        : "r"(a[0]), "r"(a[1]), "r"(a[2]), "r"(a[3]), "r"(b0), "r"(b1));
}

// -------- Whh -> B-fragment swizzle (bf16 hi/lo), exact mma.m16n8k16 B layout --------
__global__ void wfrag_kernel(const float* __restrict__ w0, const float* __restrict__ w1,
                             const float* __restrict__ w2, const float* __restrict__ w3,
                             uint32_t* __restrict__ out)
{
    int i = blockIdx.x * 256 + threadIdx.x;          // 131072 total
    int j    = i & 1;
    int lane = (i >> 1) & 31;
    int nt   = (i >> 6) & 31;
    int kt   = (i >> 11) & 3;
    int sp   = (i >> 13) & 1;
    int dir  = (i >> 14) & 1;
    int p    = i >> 15;
    const float* w = (p == 0) ? w0 : (p == 1) ? w1 : (p == 2) ? w2 : w3;
    int n = nt * 8 + (lane >> 2);
    int k = kt * 16 + (lane & 3) * 2 + j * 8;
    float x0 = w[dir * 16384 + n * 64 + k];
    float x1 = w[dir * 16384 + n * 64 + k + 1];
    __nv_bfloat16 h0 = __float2bfloat16(x0);
    __nv_bfloat16 h1 = __float2bfloat16(x1);
    if (sp == 0) out[i] = packbf(h0, h1);
    else out[i] = packbf(__float2bfloat16(x0 - __bfloat162float(h0)),
                         __float2bfloat16(x1 - __bfloat162float(h1)));
}

// ---------------- tensor-core GEMM: C[M,512] = A[M,128] * W[512,128]^T + bias ----------
// bf16x3 split, fp32 accumulate. Epilogue stages through smem so the permuted
// gate layout (phys = d*256 + lm*64 + ntg*2 + b) is written as coalesced float4 runs.
__global__ void __launch_bounds__(256, 1)
gemm_tc(const float* __restrict__ A, const float* __restrict__ W,
        const float* __restrict__ bias, float* __restrict__ C, int M)
{
    extern __shared__ uint32_t sm[];
    uint32_t* Ahi = sm;
    uint32_t* Alo = sm + 128 * 68;
    uint32_t* Whi = sm + 2 * 128 * 68;
    uint32_t* Wlo = sm + 3 * 128 * 68;

    int tid  = threadIdx.x;
    int row0 = blockIdx.x * 128;
    int col0 = blockIdx.y * 128;

#pragma unroll
    for (int i = 0; i < 16; i++) {
        int t = tid + i * 256;
        int r = t >> 5, j = t & 31;
        float4 v = make_float4(0.f, 0.f, 0.f, 0.f);
        if (row0 + r < M) v = *(const float4*)(A + (size_t)(row0 + r) * 128 + j * 4);
        uint32_t h0, l0, h1, l1;
        split2(v.x, v.y, h0, l0);
        split2(v.z, v.w, h1, l1);
        Ahi[r * 68 + j * 2]     = h0;
        Ahi[r * 68 + j * 2 + 1] = h1;
        Alo[r * 68 + j * 2]     = l0;
        Alo[r * 68 + j * 2 + 1] = l1;
    }
#pragma unroll
    for (int i = 0; i < 16; i++) {
        int t = tid + i * 256;
        int r = t >> 5, j = t & 31;
        float4 v = *(const float4*)(W + (size_t)(col0 + r) * 128 + j * 4);
        uint32_t h0, l0, h1, l1;
        split2(v.x, v.y, h0, l0);
        split2(v.z, v.w, h1, l1);
        Whi[r * 68 + j * 2]     = h0;
        Whi[r * 68 + j * 2 + 1] = h1;
        Wlo[r * 68 + j * 2]     = l0;
        Wlo[r * 68 + j * 2 + 1] = l1;
    }
    __syncthreads();

    int lane = tid & 31, warp = tid >> 5;
    int wm = warp >> 1, wn = warp & 1;
    int l4 = lane >> 2, lm = lane & 3;

    float acc[2][8][4];
#pragma unroll
    for (int mt = 0; mt < 2; mt++)
#pragma unroll
        for (int nt = 0; nt < 8; nt++)
#pragma unroll
            for (int q = 0; q < 4; q++) acc[mt][nt][q] = 0.f;

#pragma unroll
    for (int ks = 0; ks < 8; ks++) {
        int kw = ks * 8 + lm;
        uint32_t ah[2][4], al[2][4];
#pragma unroll
        for (int mt = 0; mt < 2; mt++) {
            int r = wm * 32 + mt * 16 + l4;
            ah[mt][0] = Ahi[(r)     * 68 + kw];
            ah[mt][1] = Ahi[(r + 8) * 68 + kw];
            ah[mt][2] = Ahi[(r)     * 68 + kw + 4];
            ah[mt][3] = Ahi[(r + 8) * 68 + kw + 4];
            al[mt][0] = Alo[(r)     * 68 + kw];
            al[mt][1] = Alo[(r + 8) * 68 + kw];
            al[mt][2] = Alo[(r)     * 68 + kw + 4];
            al[mt][3] = Alo[(r + 8) * 68 + kw + 4];
        }
#pragma unroll
        for (int nt = 0; nt < 8; nt++) {
            int br = wn * 64 + nt * 8 + l4;
            uint32_t bh0 = Whi[br * 68 + kw], bh1 = Whi[br * 68 + kw + 4];
            uint32_t bl0 = Wlo[br * 68 + kw], bl1 = Wlo[br * 68 + kw + 4];
#pragma unroll
            for (int mt = 0; mt < 2; mt++) {
                mma_bf16(acc[mt][nt], ah[mt], bh0, bh1);
                mma_bf16(acc[mt][nt], ah[mt], bl0, bl1);
                mma_bf16(acc[mt][nt], al[mt], bh0, bh1);
            }
        }
    }
    __syncthreads();                              // done reading B planes

    // ---- stage into smem planes: plane[lm][128 rows][36 (32+pad)] ----
    float* plane = (float*)sm;
#pragma unroll
    for (int nt = 0; nt < 8; nt++) {
        int c  = col0 + wn * 64 + nt * 8 + lm * 2;        // logical col (even)
        float b0 = bias[c], b1 = bias[c + 1];
        int cc = (wn * 8 + nt) * 2;
#pragma unroll
        for (int mt = 0; mt < 2; mt++) {
            int r = wm * 32 + mt * 16 + l4;
            *(float2*)(plane + lm * 4608 + r * 36 + cc)
                = make_float2(acc[mt][nt][0] + b0, acc[mt][nt][1] + b1);
            *(float2*)(plane + lm * 4608 + (r + 8) * 36 + cc)
                = make_float2(acc[mt][nt][2] + b0, acc[mt][nt][3] + b1);
        }
    }
    __syncthreads();

    // ---- coalesced writeout: 4 segments of 128B per row ----
    int d  = col0 >> 8;
    int s0 = (col0 & 128) >> 2;                   // 0 or 32
#pragma unroll
    for (int i = 0; i < 16; i++) {
        int idx = tid + i * 256;                  // 0..4095
        int p   = idx >> 10;                      // plane (lm)
        int rem = idx & 1023;
        int r   = rem >> 3, j4 = rem & 7;
        if (row0 + r < M) {
            float4 v = *(const float4*)(plane + p * 4608 + r * 36 + j4 * 4);
            *(float4*)(C + (size_t)(row0 + r) * 512 + d * 256 + p * 64 + s0 + j4 * 4) = v;
        }
    }
}

// ---------------- tensor-core BiLSTM + mean (q-pair grouped, spill-free) ----------------
// 256 threads = 8 warps. Warp w: dir = w&1, mtile = w>>1. Warp owns 16 (node,dir) rows and
// computes G[16,256] = H @ Whh^T via mma.m16n8k16 bf16x3, in 4 q-pair groups of 8 tiles
// (i/f/g/o for gate pair) so only 32 accumulator floats are live at once. h D-fragments
// repack register-only into double-buffered next-step A-fragments. Zero intra-step syncs.
// et = blockIdx.y selects edge type (fused neighbor launch).
template<int L, bool GATHER>
__global__ void __launch_bounds__(256, 1)
lstm_tc(const float* __restrict__ XgA, const float* __restrict__ XgB,
        const int* __restrict__ i0, const int* __restrict__ i1,
        const int* __restrict__ i2, const int* __restrict__ i3,
        const uint32_t* __restrict__ wfA, const uint32_t* __restrict__ wfB,
        float* __restrict__ o0, float* __restrict__ o1,
        float* __restrict__ o2, float* __restrict__ o3,
        int nnodes)
{
    extern __shared__ uint32_t bsm[];            // 32768: [dir][split][kt][nt][lane][2]
    int* idxs = (int*)(bsm + 32768);             // 64*L ints (neighbor only)

    int et = blockIdx.y;
    const float* Xg = (et & 1) ? XgB : XgA;
    const uint32_t* wfrag = (et & 1) ? wfB : wfA;
    const int* idx = (et == 0) ? i0 : (et == 1) ? i1 : (et == 2) ? i2 : i3;
    float* outp = (et == 0) ? o0 : (et == 1) ? o1 : (et == 2) ? o2 : o3;

    int tid = threadIdx.x;
#pragma unroll
    for (int i = 0; i < 32; i++)
        ((uint4*)bsm)[tid + i * 256] = ((const uint4*)wfrag)[tid + i * 256];
    if (GATHER) {
        for (int i = tid; i < 64 * L; i += 256) {
            int gix = blockIdx.x * 64 * L + i;
            idxs[i] = (gix < nnodes * L) ? idx[gix] : 0;
        }
    }
    __syncthreads();

    int lane = tid & 31, warp = tid >> 5;
    int dir = warp & 1, mtile = warp >> 1;
    int gr = lane >> 2, lm = lane & 3;
    int lrow0 = mtile * 16 + gr;                 // block-local row 0..63
    int gnode0 = blockIdx.x * 64 + lrow0;
    bool ok0 = gnode0 < nnodes;
    bool ok1 = gnode0 + 8 < nnodes;
    int cn0 = ok0 ? gnode0 : 0;
    int cn1 = ok1 ? gnode0 + 8 : 0;

    float cst[32], hsum[32];
#pragma unroll
    for (int q = 0; q < 32; q++) { cst[q] = 0.f; hsum[q] = 0.f; }
    uint32_t ahi[16], alo[16], nhi[16], nlo[16];

    const uint32_t* bd  = bsm + dir * 16384;     // hi split
    const uint32_t* bdl = bd + 8192;             // lo split

#pragma unroll 1
    for (int l = 0; l < L; l++) {
        int seq = dir ? (L - 1 - l) : l;
        int xr0, xr1;
        if (GATHER) {
            xr0 = ok0 ? idxs[lrow0 * L + seq] : 0;
            xr1 = ok1 ? idxs[(lrow0 + 8) * L + seq] : 0;
        } else {
            xr0 = cn0 * L + seq;
            xr1 = cn1 * L + seq;
        }
        const float* xp0 = Xg + (size_t)xr0 * 512 + (dir << 8) + lm * 64;
        const float* xp1 = Xg + (size_t)xr1 * 512 + (dir << 8) + lm * 64;

#pragma unroll
        for (int qp = 0; qp < 4; qp++) {
            // tiles in this group: nt = s*8 + 2qp + e  (s: i/f/g/o, e: gate pair)
            float acc[8][4];
#pragma unroll
            for (int s = 0; s < 4; s++) {
                float4 v0 = *(const float4*)(xp0 + s * 16 + qp * 4);
                float4 v1 = *(const float4*)(xp1 + s * 16 + qp * 4);
                acc[s * 2][0] = v0.x; acc[s * 2][1] = v0.y;
                acc[s * 2 + 1][0] = v0.z; acc[s * 2 + 1][1] = v0.w;
                acc[s * 2][2] = v1.x; acc[s * 2][3] = v1.y;
                acc[s * 2 + 1][2] = v1.z; acc[s * 2 + 1][3] = v1.w;
            }
            if (l > 0) {
#pragma unroll
                for (int kt = 0; kt < 4; kt++) {
                    const uint32_t* bk = bd  + kt * 2048 + lane * 2;
                    const uint32_t* bl = bdl + kt * 2048 + lane * 2;
#pragma unroll
                    for (int s = 0; s < 4; s++) {
#pragma unroll
                        for (int e = 0; e < 2; e++) {
                            int nt = s * 8 + 2 * qp + e;
                            uint2 bh = *(const uint2*)(bk + nt * 64);
                            uint2 bo = *(const uint2*)(bl + nt * 64);
                            mma_bf16(acc[s * 2 + e], ahi + kt * 4, bh.x, bh.y);
                            mma_bf16(acc[s * 2 + e], ahi + kt * 4, bo.x, bo.y);
                            mma_bf16(acc[s * 2 + e], alo + kt * 4, bh.x, bh.y);
                        }
                    }
                }
            }
            // elementwise gates for q = 2qp, 2qp+1 (lane-local) + D->A repack
#pragma unroll
            for (int e = 0; e < 2; e++) {
                int q = 2 * qp + e;
                float h[4];
#pragma unroll
                for (int j = 0; j < 4; j++) {
                    float ig = sigf(acc[e][j]);
                    float fg = sigf(acc[2 + e][j]);
                    float gg = tanh_f(acc[4 + e][j]);
                    float og = sigf(acc[6 + e][j]);
                    float c = fg * cst[q * 4 + j] + ig * gg;
                    cst[q * 4 + j] = c;
                    float hv = og * tanh_f(c);
                    hsum[q * 4 + j] += hv;
                    h[j] = hv;
                }
                int base = qp * 4 + e * 2;
                __nv_bfloat16 b0 = __float2bfloat16(h[0]);
                __nv_bfloat16 b1 = __float2bfloat16(h[1]);
                __nv_bfloat16 b2 = __float2bfloat16(h[2]);
                __nv_bfloat16 b3 = __float2bfloat16(h[3]);
                nhi[base]     = packbf(b0, b1);
                nhi[base + 1] = packbf(b2, b3);
                nlo[base]     = packbf(__float2bfloat16(h[0] - __bfloat162float(b0)),
                                       __float2bfloat16(h[1] - __bfloat162float(b1)));
                nlo[base + 1] = packbf(__float2bfloat16(h[2] - __bfloat162float(b2)),
                                       __float2bfloat16(h[3] - __bfloat162float(b3)));
            }
        }
        // buffer swap (register copies; old ahi fully consumed this step)
#pragma unroll
        for (int i = 0; i < 16; i++) { ahi[i] = nhi[i]; alo[i] = nlo[i]; }
    }

    float invL = 1.f / (float)L;
#pragma unroll
    for (int q = 0; q < 8; q++) {
        size_t col = dir * 64 + q * 8 + lm * 2;
        if (ok0)
            *(float2*)(outp + (size_t)gnode0 * 128 + col)
                = make_float2(hsum[q * 4] * invL, hsum[q * 4 + 1] * invL);
        if (ok1)
            *(float2*)(outp + (size_t)(gnode0 + 8) * 128 + col)
                = make_float2(hsum[q * 4 + 2] * invL, hsum[q * 4 + 3] * invL);
    }
}

// ---------------- attention combine: one warp per node ----------------
__global__ void __launch_bounds__(256)
combine_kernel(const float* __restrict__ c, const float* __restrict__ n1,
               const float* __restrict__ n2, const float* __restrict__ attn,
               float* __restrict__ out)
{
    int warp = threadIdx.x >> 5, lane = threadIdx.x & 31;
    int n = blockIdx.x * 8 + warp;
    size_t off = (size_t)n * 128 + lane * 4;
    float4 cv = *(const float4*)(c + off);
    float4 e1 = *(const float4*)(n1 + off);
    float4 e2 = *(const float4*)(n2 + off);
    float4 ac = *(const float4*)(attn + lane * 4);
    float4 ae = *(const float4*)(attn + 128 + lane * 4);

    float base = ac.x * cv.x + ac.y * cv.y + ac.z * cv.z + ac.w * cv.w;
    float d0   = ae.x * cv.x + ae.y * cv.y + ae.z * cv.z + ae.w * cv.w;
    float d1   = ae.x * e1.x + ae.y * e1.y + ae.z * e1.z + ae.w * e1.w;
    float d2   = ae.x * e2.x + ae.y * e2.y + ae.z * e2.z + ae.w * e2.w;
#pragma unroll
    for (int s = 16; s > 0; s >>= 1) {
        base += __shfl_xor_sync(0xffffffffu, base, s);
        d0   += __shfl_xor_sync(0xffffffffu, d0, s);
        d1   += __shfl_xor_sync(0xffffffffu, d1, s);
        d2   += __shfl_xor_sync(0xffffffffu, d2, s);
    }
    float s0 = base + d0, s1 = base + d1, s2 = base + d2;
    s0 = (s0 >= 0.f) ? s0 : 0.01f * s0;
    s1 = (s1 >= 0.f) ? s1 : 0.01f * s1;
    s2 = (s2 >= 0.f) ? s2 : 0.01f * s2;
    float mx = fmaxf(s0, fmaxf(s1, s2));
    float w0 = __expf(s0 - mx), w1 = __expf(s1 - mx), w2 = __expf(s2 - mx);
    float inv = __fdividef(1.f, w0 + w1 + w2);
    w0 *= inv; w1 *= inv; w2 *= inv;
    float4 o;
    o.x = w0 * cv.x + w1 * e1.x + w2 * e2.x;
    o.y = w0 * cv.y + w1 * e1.y + w2 * e2.y;
    o.z = w0 * cv.z + w1 * e1.z + w2 * e2.z;
    o.w = w0 * cv.w + w1 * e1.w + w2 * e2.w;
    *(float4*)(out + off) = o;
}

// ---------------- launch ----------------
extern "C" void kernel_launch(void* const* d_in, const int* in_sizes, int n_in,
                              void* d_out, int out_size)
{
    const float* feats_a = (const float*)d_in[0];
    const float* feats_b = (const float*)d_in[1];
    const float* Wih_ca  = (const float*)d_in[2];
    const float* Whh_ca  = (const float*)d_in[3];
    const float* b_ca    = (const float*)d_in[4];
    const float* Wih_cb  = (const float*)d_in[5];
    const float* Whh_cb  = (const float*)d_in[6];
    const float* b_cb    = (const float*)d_in[7];
    const float* Wih_na  = (const float*)d_in[8];
    const float* Whh_na  = (const float*)d_in[9];
    const float* b_na    = (const float*)d_in[10];
    const float* Wih_nb  = (const float*)d_in[11];
    const float* Whh_nb  = (const float*)d_in[12];
    const float* b_nb    = (const float*)d_in[13];
    const float* attn_a  = (const float*)d_in[14];
    const float* attn_b  = (const float*)d_in[15];
    const int* idx_a_a   = (const int*)d_in[16];
    const int* idx_b_a   = (const int*)d_in[17];
    const int* idx_a_b   = (const int*)d_in[18];
    const int* idx_b_b   = (const int*)d_in[19];
    float* out = (float*)d_out;

    float *xg, *Ga, *Gb, *ca, *cb, *naa, *nba, *nab, *nbb;
    uint32_t* wfrag;
    cudaGetSymbolAddress((void**)&xg,  g_xg);
    cudaGetSymbolAddress((void**)&Ga,  g_Ga);
    cudaGetSymbolAddress((void**)&Gb,  g_Gb);
    cudaGetSymbolAddress((void**)&ca,  g_ca);
    cudaGetSymbolAddress((void**)&cb,  g_cb);
    cudaGetSymbolAddress((void**)&naa, g_naa);
    cudaGetSymbolAddress((void**)&nba, g_nba);
    cudaGetSymbolAddress((void**)&nab, g_nab);
    cudaGetSymbolAddress((void**)&nbb, g_nbb);
    cudaGetSymbolAddress((void**)&wfrag, g_wfrag);

    const int gemm_smem = 4 * 128 * 68 * 4;                 // 139264
    const int lstm_c_smem = 32768 * 4 + 64 * L_CONT * 4;    // 132352
    const int lstm_n_smem = 32768 * 4 + 64 * K_FAN * 4;     // 135168
    cudaFuncSetAttribute((const void*)gemm_tc,
                         cudaFuncAttributeMaxDynamicSharedMemorySize, gemm_smem);
    cudaFuncSetAttribute((const void*)lstm_tc<L_CONT, false>,
                         cudaFuncAttributeMaxDynamicSharedMemorySize, lstm_c_smem);
    cudaFuncSetAttribute((const void*)lstm_tc<K_FAN, true>,
                         cudaFuncAttributeMaxDynamicSharedMemorySize, lstm_n_smem);

    // 0) Whh -> mma B-fragments (bf16 hi/lo), all four param sets
    wfrag_kernel<<<512, 256>>>(Whh_ca, Whh_cb, Whh_na, Whh_nb, wfrag);

    dim3 ggrid((30000 + 127) / 128, 4);        // M=30000 rows per GEMM launch
    const int cblk = (CCHUNK + 63) / 64;       // LSTM blocks per content chunk
    const int nblk = (N_NODES + 63) / 64;      // LSTM blocks per neighbor type

    // 1) content type a: chunked so xg stays L2-resident between GEMM and LSTM
    for (int c = 0; c < NCHUNK; c++) {
        gemm_tc<<<ggrid, 256, gemm_smem>>>(feats_a + (size_t)c * CCHUNK * L_CONT * 128,
                                           Wih_ca, b_ca, xg, CCHUNK * L_CONT);
        lstm_tc<L_CONT, false><<<cblk, 256, lstm_c_smem>>>(
            xg, xg, nullptr, nullptr, nullptr, nullptr,
            wfrag + 0 * 32768, wfrag + 0 * 32768,
            ca + (size_t)c * CCHUNK * 128, nullptr, nullptr, nullptr, CCHUNK);
    }
    // 2) content type b
    for (int c = 0; c < NCHUNK; c++) {
        gemm_tc<<<ggrid, 256, gemm_smem>>>(feats_b + (size_t)c * CCHUNK * L_CONT * 128,
                                           Wih_cb, b_cb, xg, CCHUNK * L_CONT);
        lstm_tc<L_CONT, false><<<cblk, 256, lstm_c_smem>>>(
            xg, xg, nullptr, nullptr, nullptr, nullptr,
            wfrag + 1 * 32768, wfrag + 1 * 32768,
            cb + (size_t)c * CCHUNK * 128, nullptr, nullptr, nullptr, CCHUNK);
    }

    // 3) neighbor gate tables: G_src = c_src @ Wih_n^T + b_n (gather commutes with GEMM)
    gemm_tc<<<ggrid, 256, gemm_smem>>>(ca, Wih_na, b_na, Ga, N_NODES);
    gemm_tc<<<ggrid, 256, gemm_smem>>>(cb, Wih_nb, b_nb, Gb, N_NODES);

    // 4) all four neighbor BiLSTMs in ONE fused launch (blockIdx.y = edge type)
    lstm_tc<K_FAN, true><<<dim3(nblk, 4), 256, lstm_n_smem>>>(
        Ga, Gb, idx_a_a, idx_b_a, idx_a_b, idx_b_b,
        wfrag + 2 * 32768, wfrag + 3 * 32768,
        naa, nba, nab, nbb, N_NODES);

    // 5) attention combine -> out[2, N, 128]
    combine_kernel<<<N_NODES / 8, 256>>>(ca, naa, nba, attn_a, out);
    combine_kernel<<<N_NODES / 8, 256>>>(cb, nab, nbb, attn_b, out + (size_t)N_NODES * 128);
}

// round 11
// speedup vs baseline: 2.0482x; 1.1030x over previous
#include <cuda_runtime.h>
#include <cuda_bf16.h>
#include <cuda_fp16.h>
#include <cstdint>

#define N_NODES 30000
#define L_CONT  5
#define K_FAN   16
#define CCHUNK  6000          // content chunk (xg chunk = 61.4 MB -> L2 resident)
#define NCHUNK  5

// ---------------- device scratch (static: no allocations allowed) ----------------
__device__ float    g_xg [CCHUNK * L_CONT * 512]; // content input-gate chunk buffer (permuted+bias)
__device__ float    g_Ga [N_NODES * 512];         // neighbor gate table, src type a (permuted+bias)
__device__ float    g_Gb [N_NODES * 512];         // neighbor gate table, src type b
__device__ float    g_ca [N_NODES * 128];
__device__ float    g_cb [N_NODES * 128];
__device__ float    g_naa[N_NODES * 128];
__device__ float    g_nba[N_NODES * 128];
__device__ float    g_nab[N_NODES * 128];
__device__ float    g_nbb[N_NODES * 128];
__device__ uint32_t g_wfrag[4 * 16384];           // fp16 Whh B-fragments: [p][dir][kt][nt][lane][2]

// ---------------- helpers ----------------
__device__ __forceinline__ float sigf(float x) {
    return __fdividef(1.f, 1.f + __expf(-x));
}
__device__ __forceinline__ float tanh_f(float x) {
    return __fdividef(2.f, 1.f + __expf(-2.f * x)) - 1.f;
}
__device__ __forceinline__ uint32_t packbf(__nv_bfloat16 a, __nv_bfloat16 b) {
    __nv_bfloat162 v; v.x = a; v.y = b;
    return *(uint32_t*)&v;
}
__device__ __forceinline__ uint32_t packh(float a, float b) {
    __half2 v = __floats2half2_rn(a, b);
    return *(uint32_t*)&v;
}
__device__ __forceinline__ void split2(float x, float y, uint32_t& hi, uint32_t& lo) {
    __nv_bfloat16 hx = __float2bfloat16(x);
    __nv_bfloat16 hy = __float2bfloat16(y);
    hi = packbf(hx, hy);
    lo = packbf(__float2bfloat16(x - __bfloat162float(hx)),
                __float2bfloat16(y - __bfloat162float(hy)));
}
__device__ __forceinline__ void mma_bf16(float* d, const uint32_t* a, uint32_t b0, uint32_t b1) {
    asm volatile(
        "mma.sync.aligned.m16n8k16.row.col.f32.bf16.bf16.f32 "
        "{%0,%1,%2,%3}, {%4,%5,%6,%7}, {%8,%9}, {%0,%1,%2,%3};\n"
        : "+f"(d[0]), "+f"(d[1]), "+f"(d[2]), "+f"(d[3])
        : "r"(a[0]), "r"(a[1]), "r"(a[2]), "r"(a[3]), "r"(b0), "r"(b1));
}
__device__ __forceinline__ void mma_f16(float* d, const uint32_t* a, uint32_t b0, uint32_t b1) {
    asm volatile(
        "mma.sync.aligned.m16n8k16.row.col.f32.f16.f16.f32 "
        "{%0,%1,%2,%3}, {%4,%5,%6,%7}, {%8,%9}, {%0,%1,%2,%3};\n"
        : "+f"(d[0]), "+f"(d[1]), "+f"(d[2]), "+f"(d[3])
        : "r"(a[0]), "r"(a[1]), "r"(a[2]), "r"(a[3]), "r"(b0), "r"(b1));
}

// -------- Whh -> fp16 B-fragment swizzle, exact mma.m16n8k16 B layout --------
// out[p][dir][kt][nt][lane][j]: n = nt*8 + (lane>>2), k = kt*16 + (lane&3)*2 + j*8
__global__ void wfrag_kernel(const float* __restrict__ w0, const float* __restrict__ w1,
                             const float* __restrict__ w2, const float* __restrict__ w3,
                             uint32_t* __restrict__ out)
{
    int i = blockIdx.x * 256 + threadIdx.x;          // 65536 total
    int j    = i & 1;
    int lane = (i >> 1) & 31;
    int nt   = (i >> 6) & 31;
    int kt   = (i >> 11) & 3;
    int dir  = (i >> 13) & 1;
    int p    = i >> 14;
    const float* w = (p == 0) ? w0 : (p == 1) ? w1 : (p == 2) ? w2 : w3;
    int n = nt * 8 + (lane >> 2);
    int k = kt * 16 + (lane & 3) * 2 + j * 8;
    out[i] = packh(w[dir * 16384 + n * 64 + k], w[dir * 16384 + n * 64 + k + 1]);
}

// ---------------- tensor-core GEMM: C[M,512] = A[M,128] * W[512,128]^T + bias ----------
// bf16x3 split, fp32 accumulate. Epilogue stages through smem so the permuted
// gate layout (phys = d*256 + lm*64 + ntg*2 + b) is written as coalesced float4 runs.
__global__ void __launch_bounds__(256, 1)
gemm_tc(const float* __restrict__ A, const float* __restrict__ W,
        const float* __restrict__ bias, float* __restrict__ C, int M)
{
    extern __shared__ uint32_t sm[];
    uint32_t* Ahi = sm;
    uint32_t* Alo = sm + 128 * 68;
    uint32_t* Whi = sm + 2 * 128 * 68;
    uint32_t* Wlo = sm + 3 * 128 * 68;

    int tid  = threadIdx.x;
    int row0 = blockIdx.x * 128;
    int col0 = blockIdx.y * 128;

#pragma unroll
    for (int i = 0; i < 16; i++) {
        int t = tid + i * 256;
        int r = t >> 5, j = t & 31;
        float4 v = make_float4(0.f, 0.f, 0.f, 0.f);
        if (row0 + r < M) v = *(const float4*)(A + (size_t)(row0 + r) * 128 + j * 4);
        uint32_t h0, l0, h1, l1;
        split2(v.x, v.y, h0, l0);
        split2(v.z, v.w, h1, l1);
        Ahi[r * 68 + j * 2]     = h0;
        Ahi[r * 68 + j * 2 + 1] = h1;
        Alo[r * 68 + j * 2]     = l0;
        Alo[r * 68 + j * 2 + 1] = l1;
    }
#pragma unroll
    for (int i = 0; i < 16; i++) {
        int t = tid + i * 256;
        int r = t >> 5, j = t & 31;
        float4 v = *(const float4*)(W + (size_t)(col0 + r) * 128 + j * 4);
        uint32_t h0, l0, h1, l1;
        split2(v.x, v.y, h0, l0);
        split2(v.z, v.w, h1, l1);
        Whi[r * 68 + j * 2]     = h0;
        Whi[r * 68 + j * 2 + 1] = h1;
        Wlo[r * 68 + j * 2]     = l0;
        Wlo[r * 68 + j * 2 + 1] = l1;
    }
    __syncthreads();

    int lane = tid & 31, warp = tid >> 5;
    int wm = warp >> 1, wn = warp & 1;
    int l4 = lane >> 2, lm = lane & 3;

    float acc[2][8][4];
#pragma unroll
    for (int mt = 0; mt < 2; mt++)
#pragma unroll
        for (int nt = 0; nt < 8; nt++)
#pragma unroll
            for (int q = 0; q < 4; q++) acc[mt][nt][q] = 0.f;

#pragma unroll
    for (int ks = 0; ks < 8; ks++) {
        int kw = ks * 8 + lm;
        uint32_t ah[2][4], al[2][4];
#pragma unroll
        for (int mt = 0; mt < 2; mt++) {
            int r = wm * 32 + mt * 16 + l4;
            ah[mt][0] = Ahi[(r)     * 68 + kw];
            ah[mt][1] = Ahi[(r + 8) * 68 + kw];
            ah[mt][2] = Ahi[(r)     * 68 + kw + 4];
            ah[mt][3] = Ahi[(r + 8) * 68 + kw + 4];
            al[mt][0] = Alo[(r)     * 68 + kw];
            al[mt][1] = Alo[(r + 8) * 68 + kw];
            al[mt][2] = Alo[(r)     * 68 + kw + 4];
            al[mt][3] = Alo[(r + 8) * 68 + kw + 4];
        }
#pragma unroll
        for (int nt = 0; nt < 8; nt++) {
            int br = wn * 64 + nt * 8 + l4;
            uint32_t bh0 = Whi[br * 68 + kw], bh1 = Whi[br * 68 + kw + 4];
            uint32_t bl0 = Wlo[br * 68 + kw], bl1 = Wlo[br * 68 + kw + 4];
#pragma unroll
            for (int mt = 0; mt < 2; mt++) {
                mma_bf16(acc[mt][nt], ah[mt], bh0, bh1);
                mma_bf16(acc[mt][nt], ah[mt], bl0, bl1);
                mma_bf16(acc[mt][nt], al[mt], bh0, bh1);
            }
        }
    }
    __syncthreads();                              // done reading B planes

    // ---- stage into smem planes: plane[lm][128 rows][36 (32+pad)] ----
    float* plane = (float*)sm;
#pragma unroll
    for (int nt = 0; nt < 8; nt++) {
        int c  = col0 + wn * 64 + nt * 8 + lm * 2;        // logical col (even)
        float b0 = bias[c], b1 = bias[c + 1];
        int cc = (wn * 8 + nt) * 2;
#pragma unroll
        for (int mt = 0; mt < 2; mt++) {
            int r = wm * 32 + mt * 16 + l4;
            *(float2*)(plane + lm * 4608 + r * 36 + cc)
                = make_float2(acc[mt][nt][0] + b0, acc[mt][nt][1] + b1);
            *(float2*)(plane + lm * 4608 + (r + 8) * 36 + cc)
                = make_float2(acc[mt][nt][2] + b0, acc[mt][nt][3] + b1);
        }
    }
    __syncthreads();

    // ---- coalesced writeout: 4 segments of 128B per row ----
    int d  = col0 >> 8;
    int s0 = (col0 & 128) >> 2;                   // 0 or 32
#pragma unroll
    for (int i = 0; i < 16; i++) {
        int idx = tid + i * 256;                  // 0..4095
        int p   = idx >> 10;                      // plane (lm)
        int rem = idx & 1023;
        int r   = rem >> 3, j4 = rem & 7;
        if (row0 + r < M) {
            float4 v = *(const float4*)(plane + p * 4608 + r * 36 + j4 * 4);
            *(float4*)(C + (size_t)(row0 + r) * 512 + d * 256 + p * 64 + s0 + j4 * 4) = v;
        }
    }
}

// ---------------- tensor-core BiLSTM + mean (fp16 single-pass recurrence) ----------------
// 256 threads = 8 warps. Warp w: dir = w&1, mtile = w>>1. Warp owns 16 (node,dir) rows and
// computes G[16,256] = H @ Whh^T via mma.m16n8k16 fp16 (h in (-1,1), Whh ~ N(0,0.01):
// fp16's 11-bit mantissa keeps gate error ~1e-4, 10x under tolerance). 4 q-pair groups of
// 8 acc tiles keep registers spill-free. h D-fragments repack register-only into
// double-buffered next-step A-fragments. Zero intra-step syncs.
template<int L, bool GATHER>
__global__ void __launch_bounds__(256, 1)
lstm_tc(const float* __restrict__ XgA, const float* __restrict__ XgB,
        const int* __restrict__ i0, const int* __restrict__ i1,
        const int* __restrict__ i2, const int* __restrict__ i3,
        const uint32_t* __restrict__ wfA, const uint32_t* __restrict__ wfB,
        float* __restrict__ o0, float* __restrict__ o1,
        float* __restrict__ o2, float* __restrict__ o3,
        int nnodes)
{
    extern __shared__ uint32_t bsm[];            // 16384: [dir][kt][nt][lane][2] fp16
    int* idxs = (int*)(bsm + 16384);             // 64*L ints (neighbor only)

    int et = blockIdx.y;
    const float* Xg = (et & 1) ? XgB : XgA;
    const uint32_t* wfrag = (et & 1) ? wfB : wfA;
    const int* idx = (et == 0) ? i0 : (et == 1) ? i1 : (et == 2) ? i2 : i3;
    float* outp = (et == 0) ? o0 : (et == 1) ? o1 : (et == 2) ? o2 : o3;

    int tid = threadIdx.x;
#pragma unroll
    for (int i = 0; i < 16; i++)
        ((uint4*)bsm)[tid + i * 256] = ((const uint4*)wfrag)[tid + i * 256];
    if (GATHER) {
        for (int i = tid; i < 64 * L; i += 256) {
            int gix = blockIdx.x * 64 * L + i;
            idxs[i] = (gix < nnodes * L) ? idx[gix] : 0;
        }
    }
    __syncthreads();

    int lane = tid & 31, warp = tid >> 5;
    int dir = warp & 1, mtile = warp >> 1;
    int gr = lane >> 2, lm = lane & 3;
    int lrow0 = mtile * 16 + gr;                 // block-local row 0..63
    int gnode0 = blockIdx.x * 64 + lrow0;
    bool ok0 = gnode0 < nnodes;
    bool ok1 = gnode0 + 8 < nnodes;
    int cn0 = ok0 ? gnode0 : 0;
    int cn1 = ok1 ? gnode0 + 8 : 0;

    float cst[32], hsum[32];
#pragma unroll
    for (int q = 0; q < 32; q++) { cst[q] = 0.f; hsum[q] = 0.f; }
    uint32_t afr[16], nfr[16];

    const uint32_t* bd = bsm + dir * 8192;       // [kt][nt][lane][2]

#pragma unroll 1
    for (int l = 0; l < L; l++) {
        int seq = dir ? (L - 1 - l) : l;
        int xr0, xr1;
        if (GATHER) {
            xr0 = ok0 ? idxs[lrow0 * L + seq] : 0;
            xr1 = ok1 ? idxs[(lrow0 + 8) * L + seq] : 0;
        } else {
            xr0 = cn0 * L + seq;
            xr1 = cn1 * L + seq;
        }
        const float* xp0 = Xg + (size_t)xr0 * 512 + (dir << 8) + lm * 64;
        const float* xp1 = Xg + (size_t)xr1 * 512 + (dir << 8) + lm * 64;

#pragma unroll
        for (int qp = 0; qp < 4; qp++) {
            // tiles in this group: nt = s*8 + 2qp + e  (s: i/f/g/o, e: gate pair)
            float acc[8][4];
#pragma unroll
            for (int s = 0; s < 4; s++) {
                float4 v0 = *(const float4*)(xp0 + s * 16 + qp * 4);
                float4 v1 = *(const float4*)(xp1 + s * 16 + qp * 4);
                acc[s * 2][0] = v0.x; acc[s * 2][1] = v0.y;
                acc[s * 2 + 1][0] = v0.z; acc[s * 2 + 1][1] = v0.w;
                acc[s * 2][2] = v1.x; acc[s * 2][3] = v1.y;
                acc[s * 2 + 1][2] = v1.z; acc[s * 2 + 1][3] = v1.w;
            }
            if (l > 0) {
#pragma unroll
                for (int kt = 0; kt < 4; kt++) {
                    const uint32_t* bk = bd + kt * 2048 + lane * 2;
#pragma unroll
                    for (int s = 0; s < 4; s++) {
#pragma unroll
                        for (int e = 0; e < 2; e++) {
                            int nt = s * 8 + 2 * qp + e;
                            uint2 bh = *(const uint2*)(bk + nt * 64);
                            mma_f16(acc[s * 2 + e], afr + kt * 4, bh.x, bh.y);
                        }
                    }
                }
            }
            // elementwise gates for q = 2qp, 2qp+1 (lane-local) + D->A repack
#pragma unroll
            for (int e = 0; e < 2; e++) {
                int q = 2 * qp + e;
                float h[4];
#pragma unroll
                for (int j = 0; j < 4; j++) {
                    float ig = sigf(acc[e][j]);
                    float fg = sigf(acc[2 + e][j]);
                    float gg = tanh_f(acc[4 + e][j]);
                    float og = sigf(acc[6 + e][j]);
                    float c = fg * cst[q * 4 + j] + ig * gg;
                    cst[q * 4 + j] = c;
                    float hv = og * tanh_f(c);
                    hsum[q * 4 + j] += hv;
                    h[j] = hv;
                }
                int base = qp * 4 + e * 2;
                nfr[base]     = packh(h[0], h[1]);
                nfr[base + 1] = packh(h[2], h[3]);
            }
        }
        // buffer swap (register copies; old afr fully consumed this step)
#pragma unroll
        for (int i = 0; i < 16; i++) afr[i] = nfr[i];
    }

    float invL = 1.f / (float)L;
#pragma unroll
    for (int q = 0; q < 8; q++) {
        size_t col = dir * 64 + q * 8 + lm * 2;
        if (ok0)
            *(float2*)(outp + (size_t)gnode0 * 128 + col)
                = make_float2(hsum[q * 4] * invL, hsum[q * 4 + 1] * invL);
        if (ok1)
            *(float2*)(outp + (size_t)(gnode0 + 8) * 128 + col)
                = make_float2(hsum[q * 4 + 2] * invL, hsum[q * 4 + 3] * invL);
    }
}

// ---------------- attention combine: one warp per node ----------------
__global__ void __launch_bounds__(256)
combine_kernel(const float* __restrict__ c, const float* __restrict__ n1,
               const float* __restrict__ n2, const float* __restrict__ attn,
               float* __restrict__ out)
{
    int warp = threadIdx.x >> 5, lane = threadIdx.x & 31;
    int n = blockIdx.x * 8 + warp;
    size_t off = (size_t)n * 128 + lane * 4;
    float4 cv = *(const float4*)(c + off);
    float4 e1 = *(const float4*)(n1 + off);
    float4 e2 = *(const float4*)(n2 + off);
    float4 ac = *(const float4*)(attn + lane * 4);
    float4 ae = *(const float4*)(attn + 128 + lane * 4);

    float base = ac.x * cv.x + ac.y * cv.y + ac.z * cv.z + ac.w * cv.w;
    float d0   = ae.x * cv.x + ae.y * cv.y + ae.z * cv.z + ae.w * cv.w;
    float d1   = ae.x * e1.x + ae.y * e1.y + ae.z * e1.z + ae.w * e1.w;
    float d2   = ae.x * e2.x + ae.y * e2.y + ae.z * e2.z + ae.w * e2.w;
#pragma unroll
    for (int s = 16; s > 0; s >>= 1) {
        base += __shfl_xor_sync(0xffffffffu, base, s);
        d0   += __shfl_xor_sync(0xffffffffu, d0, s);
        d1   += __shfl_xor_sync(0xffffffffu, d1, s);
        d2   += __shfl_xor_sync(0xffffffffu, d2, s);
    }
    float s0 = base + d0, s1 = base + d1, s2 = base + d2;
    s0 = (s0 >= 0.f) ? s0 : 0.01f * s0;
    s1 = (s1 >= 0.f) ? s1 : 0.01f * s1;
    s2 = (s2 >= 0.f) ? s2 : 0.01f * s2;
    float mx = fmaxf(s0, fmaxf(s1, s2));
    float w0 = __expf(s0 - mx), w1 = __expf(s1 - mx), w2 = __expf(s2 - mx);
    float inv = __fdividef(1.f, w0 + w1 + w2);
    w0 *= inv; w1 *= inv; w2 *= inv;
    float4 o;
    o.x = w0 * cv.x + w1 * e1.x + w2 * e2.x;
    o.y = w0 * cv.y + w1 * e1.y + w2 * e2.y;
    o.z = w0 * cv.z + w1 * e1.z + w2 * e2.z;
    o.w = w0 * cv.w + w1 * e1.w + w2 * e2.w;
    *(float4*)(out + off) = o;
}

// ---------------- launch ----------------
extern "C" void kernel_launch(void* const* d_in, const int* in_sizes, int n_in,
                              void* d_out, int out_size)
{
    const float* feats_a = (const float*)d_in[0];
    const float* feats_b = (const float*)d_in[1];
    const float* Wih_ca  = (const float*)d_in[2];
    const float* Whh_ca  = (const float*)d_in[3];
    const float* b_ca    = (const float*)d_in[4];
    const float* Wih_cb  = (const float*)d_in[5];
    const float* Whh_cb  = (const float*)d_in[6];
    const float* b_cb    = (const float*)d_in[7];
    const float* Wih_na  = (const float*)d_in[8];
    const float* Whh_na  = (const float*)d_in[9];
    const float* b_na    = (const float*)d_in[10];
    const float* Wih_nb  = (const float*)d_in[11];
    const float* Whh_nb  = (const float*)d_in[12];
    const float* b_nb    = (const float*)d_in[13];
    const float* attn_a  = (const float*)d_in[14];
    const float* attn_b  = (const float*)d_in[15];
    const int* idx_a_a   = (const int*)d_in[16];
    const int* idx_b_a   = (const int*)d_in[17];
    const int* idx_a_b   = (const int*)d_in[18];
    const int* idx_b_b   = (const int*)d_in[19];
    float* out = (float*)d_out;

    float *xg, *Ga, *Gb, *ca, *cb, *naa, *nba, *nab, *nbb;
    uint32_t* wfrag;
    cudaGetSymbolAddress((void**)&xg,  g_xg);
    cudaGetSymbolAddress((void**)&Ga,  g_Ga);
    cudaGetSymbolAddress((void**)&Gb,  g_Gb);
    cudaGetSymbolAddress((void**)&ca,  g_ca);
    cudaGetSymbolAddress((void**)&cb,  g_cb);
    cudaGetSymbolAddress((void**)&naa, g_naa);
    cudaGetSymbolAddress((void**)&nba, g_nba);
    cudaGetSymbolAddress((void**)&nab, g_nab);
    cudaGetSymbolAddress((void**)&nbb, g_nbb);
    cudaGetSymbolAddress((void**)&wfrag, g_wfrag);

    const int gemm_smem = 4 * 128 * 68 * 4;                 // 139264
    const int lstm_c_smem = 16384 * 4 + 64 * L_CONT * 4;    // 66816
    const int lstm_n_smem = 16384 * 4 + 64 * K_FAN * 4;     // 69632
    cudaFuncSetAttribute((const void*)gemm_tc,
                         cudaFuncAttributeMaxDynamicSharedMemorySize, gemm_smem);
    cudaFuncSetAttribute((const void*)lstm_tc<L_CONT, false>,
                         cudaFuncAttributeMaxDynamicSharedMemorySize, lstm_c_smem);
    cudaFuncSetAttribute((const void*)lstm_tc<K_FAN, true>,
                         cudaFuncAttributeMaxDynamicSharedMemorySize, lstm_n_smem);

    // 0) Whh -> fp16 mma B-fragments, all four param sets
    wfrag_kernel<<<256, 256>>>(Whh_ca, Whh_cb, Whh_na, Whh_nb, wfrag);

    dim3 ggrid((30000 + 127) / 128, 4);        // M=30000 rows per GEMM launch
    const int cblk = (CCHUNK + 63) / 64;       // LSTM blocks per content chunk
    const int nblk = (N_NODES + 63) / 64;      // LSTM blocks per neighbor type

    // 1) content type a: chunked so xg stays L2-resident between GEMM and LSTM
    for (int c = 0; c < NCHUNK; c++) {
        gemm_tc<<<ggrid, 256, gemm_smem>>>(feats_a + (size_t)c * CCHUNK * L_CONT * 128,
                                           Wih_ca, b_ca, xg, CCHUNK * L_CONT);
        lstm_tc<L_CONT, false><<<cblk, 256, lstm_c_smem>>>(
            xg, xg, nullptr, nullptr, nullptr, nullptr,
            wfrag + 0 * 16384, wfrag + 0 * 16384,
            ca + (size_t)c * CCHUNK * 128, nullptr, nullptr, nullptr, CCHUNK);
    }
    // 2) content type b
    for (int c = 0; c < NCHUNK; c++) {
        gemm_tc<<<ggrid, 256, gemm_smem>>>(feats_b + (size_t)c * CCHUNK * L_CONT * 128,
                                           Wih_cb, b_cb, xg, CCHUNK * L_CONT);
        lstm_tc<L_CONT, false><<<cblk, 256, lstm_c_smem>>>(
            xg, xg, nullptr, nullptr, nullptr, nullptr,
            wfrag + 1 * 16384, wfrag + 1 * 16384,
            cb + (size_t)c * CCHUNK * 128, nullptr, nullptr, nullptr, CCHUNK);
    }

    // 3) neighbor gate tables: G_src = c_src @ Wih_n^T + b_n (gather commutes with GEMM)
    gemm_tc<<<ggrid, 256, gemm_smem>>>(ca, Wih_na, b_na, Ga, N_NODES);
    gemm_tc<<<ggrid, 256, gemm_smem>>>(cb, Wih_nb, b_nb, Gb, N_NODES);

    // 4) all four neighbor BiLSTMs in ONE fused launch (blockIdx.y = edge type)
    lstm_tc<K_FAN, true><<<dim3(nblk, 4), 256, lstm_n_smem>>>(
        Ga, Gb, idx_a_a, idx_b_a, idx_a_b, idx_b_b,
        wfrag + 2 * 16384, wfrag + 3 * 16384,
        naa, nba, nab, nbb, N_NODES);

    // 5) attention combine -> out[2, N, 128]
    combine_kernel<<<N_NODES / 8, 256>>>(ca, naa, nba, attn_a, out);
    combine_kernel<<<N_NODES / 8, 256>>>(cb, nab, nbb, attn_b, out + (size_t)N_NODES * 128);
}

// round 14
// speedup vs baseline: 2.0859x; 1.0184x over previous
#include <cuda_runtime.h>
#include <cuda_bf16.h>
#include <cuda_fp16.h>
#include <cstdint>

#define N_NODES 30000
#define L_CONT  5
#define K_FAN   16
#define CCHUNK  6000          // content chunk (xg chunk = 61.4 MB -> L2 resident)
#define NCHUNK  5

// ---------------- device scratch (static: no allocations allowed) ----------------
__device__ float    g_xg [CCHUNK * L_CONT * 512]; // content input-gate chunk buffer (permuted+bias)
__device__ float    g_Ga [N_NODES * 512];         // neighbor gate table, src type a (permuted+bias)
__device__ float    g_Gb [N_NODES * 512];         // neighbor gate table, src type b
__device__ float    g_ca [N_NODES * 128];
__device__ float    g_cb [N_NODES * 128];
__device__ float    g_naa[N_NODES * 128];
__device__ float    g_nba[N_NODES * 128];
__device__ float    g_nab[N_NODES * 128];
__device__ float    g_nbb[N_NODES * 128];
__device__ uint32_t g_wfrag[4 * 16384];           // fp16 Whh B-fragments: [p][dir][kt][nt][lane][2]

// ---------------- helpers ----------------
__device__ __forceinline__ float tanh_fast(float x) {
    float y; asm("tanh.approx.f32 %0, %1;" : "=f"(y) : "f"(x)); return y;
}
__device__ __forceinline__ float sig_fast(float x) {
    return fmaf(0.5f, tanh_fast(0.5f * x), 0.5f);   // sigmoid via single MUFU tanh
}
__device__ __forceinline__ uint32_t packbf(__nv_bfloat16 a, __nv_bfloat16 b) {
    __nv_bfloat162 v; v.x = a; v.y = b;
    return *(uint32_t*)&v;
}
__device__ __forceinline__ uint32_t packh(float a, float b) {
    __half2 v = __floats2half2_rn(a, b);
    return *(uint32_t*)&v;
}
__device__ __forceinline__ void split2(float x, float y, uint32_t& hi, uint32_t& lo) {
    __nv_bfloat16 hx = __float2bfloat16(x);
    __nv_bfloat16 hy = __float2bfloat16(y);
    hi = packbf(hx, hy);
    lo = packbf(__float2bfloat16(x - __bfloat162float(hx)),
                __float2bfloat16(y - __bfloat162float(hy)));
}
__device__ __forceinline__ void mma_bf16(float* d, const uint32_t* a, uint32_t b0, uint32_t b1) {
    asm volatile(
        "mma.sync.aligned.m16n8k16.row.col.f32.bf16.bf16.f32 "
        "{%0,%1,%2,%3}, {%4,%5,%6,%7}, {%8,%9}, {%0,%1,%2,%3};\n"
        : "+f"(d[0]), "+f"(d[1]), "+f"(d[2]), "+f"(d[3])
        : "r"(a[0]), "r"(a[1]), "r"(a[2]), "r"(a[3]), "r"(b0), "r"(b1));
}
__device__ __forceinline__ void mma_f16(float* d, const uint32_t* a, uint32_t b0, uint32_t b1) {
    asm volatile(
        "mma.sync.aligned.m16n8k16.row.col.f32.f16.f16.f32 "
        "{%0,%1,%2,%3}, {%4,%5,%6,%7}, {%8,%9}, {%0,%1,%2,%3};\n"
        : "+f"(d[0]), "+f"(d[1]), "+f"(d[2]), "+f"(d[3])
        : "r"(a[0]), "r"(a[1]), "r"(a[2]), "r"(a[3]), "r"(b0), "r"(b1));
}
__device__ __forceinline__ void ldsm_x4(uint32_t& r0, uint32_t& r1, uint32_t& r2, uint32_t& r3,
                                        uint32_t addr) {
    asm volatile("ldmatrix.sync.aligned.m8n8.x4.shared.b16 {%0,%1,%2,%3}, [%4];"
                 : "=r"(r0), "=r"(r1), "=r"(r2), "=r"(r3) : "r"(addr));
}

// -------- Whh -> fp16 B-fragment swizzle, exact mma.m16n8k16 B layout --------
// out[p][dir][kt][nt][lane][j]: n = nt*8 + (lane>>2), k = kt*16 + (lane&3)*2 + j*8
__global__ void wfrag_kernel(const float* __restrict__ w0, const float* __restrict__ w1,
                             const float* __restrict__ w2, const float* __restrict__ w3,
                             uint32_t* __restrict__ out)
{
    int i = blockIdx.x * 256 + threadIdx.x;          // 65536 total
    int j    = i & 1;
    int lane = (i >> 1) & 31;
    int nt   = (i >> 6) & 31;
    int kt   = (i >> 11) & 3;
    int dir  = (i >> 13) & 1;
    int p    = i >> 14;
    const float* w = (p == 0) ? w0 : (p == 1) ? w1 : (p == 2) ? w2 : w3;
    int n = nt * 8 + (lane >> 2);
    int k = kt * 16 + (lane & 3) * 2 + j * 8;
    out[i] = packh(w[dir * 16384 + n * 64 + k], w[dir * 16384 + n * 64 + k + 1]);
}

// ---------------- tensor-core GEMM: C[M,512] = A[M,128] * W[512,128]^T + bias ----------
// bf16x3 split, fp32 accumulate. Fragments loaded with ldmatrix.x4 (12 shared-load
// instructions per warp per k-step vs 48 scalar LDS -> MMA-bound). Epilogue stages
// through smem so the permuted gate layout is written as coalesced float4 runs.
__global__ void __launch_bounds__(256, 1)
gemm_tc(const float* __restrict__ A, const float* __restrict__ W,
        const float* __restrict__ bias, float* __restrict__ C, int M)
{
    extern __shared__ uint32_t sm[];
    uint32_t* Ahi = sm;
    uint32_t* Alo = sm + 128 * 68;
    uint32_t* Whi = sm + 2 * 128 * 68;
    uint32_t* Wlo = sm + 3 * 128 * 68;

    int tid  = threadIdx.x;
    int row0 = blockIdx.x * 128;
    int col0 = blockIdx.y * 128;

#pragma unroll
    for (int i = 0; i < 16; i++) {
        int t = tid + i * 256;
        int r = t >> 5, j = t & 31;
        float4 v = make_float4(0.f, 0.f, 0.f, 0.f);
        if (row0 + r < M) v = *(const float4*)(A + (size_t)(row0 + r) * 128 + j * 4);
        uint32_t h0, l0, h1, l1;
        split2(v.x, v.y, h0, l0);
        split2(v.z, v.w, h1, l1);
        Ahi[r * 68 + j * 2]     = h0;
        Ahi[r * 68 + j * 2 + 1] = h1;
        Alo[r * 68 + j * 2]     = l0;
        Alo[r * 68 + j * 2 + 1] = l1;
    }
#pragma unroll
    for (int i = 0; i < 16; i++) {
        int t = tid + i * 256;
        int r = t >> 5, j = t & 31;
        float4 v = *(const float4*)(W + (size_t)(col0 + r) * 128 + j * 4);
        uint32_t h0, l0, h1, l1;
        split2(v.x, v.y, h0, l0);
        split2(v.z, v.w, h1, l1);
        Whi[r * 68 + j * 2]     = h0;
        Whi[r * 68 + j * 2 + 1] = h1;
        Wlo[r * 68 + j * 2]     = l0;
        Wlo[r * 68 + j * 2 + 1] = l1;
    }
    __syncthreads();

    int lane = tid & 31, warp = tid >> 5;
    int wm = warp >> 1, wn = warp & 1;
    int l4 = lane >> 2, lm = lane & 3;

    // ldmatrix per-lane address components
    uint32_t sbase = (uint32_t)__cvta_generic_to_shared(sm);
    int rA = (lane & 7) + ((lane >> 3) & 1) * 8;   // A: tiles 0/1 = rows, 2/3 = k+8
    int kA = ((lane >> 4) & 1) * 4;
    int rB = (lane & 7) + ((lane >> 4) & 1) * 8;   // B: tiles 0/1 = nt0 (k,k+8), 2/3 = nt1
    int kB = ((lane >> 3) & 1) * 4;

    float acc[2][8][4];
#pragma unroll
    for (int mt = 0; mt < 2; mt++)
#pragma unroll
        for (int nt = 0; nt < 8; nt++)
#pragma unroll
            for (int q = 0; q < 4; q++) acc[mt][nt][q] = 0.f;

#pragma unroll
    for (int ks = 0; ks < 8; ks++) {
        uint32_t ah[2][4], al[2][4];
#pragma unroll
        for (int mt = 0; mt < 2; mt++) {
            uint32_t rowA = (wm * 32 + mt * 16 + rA) * 68 + ks * 8 + kA;
            ldsm_x4(ah[mt][0], ah[mt][1], ah[mt][2], ah[mt][3], sbase + 4 * rowA);
            ldsm_x4(al[mt][0], al[mt][1], al[mt][2], al[mt][3],
                    sbase + 4 * (8704 + rowA));
        }
#pragma unroll
        for (int g = 0; g < 4; g++) {
            uint32_t rowB = (wn * 64 + g * 16 + rB) * 68 + ks * 8 + kB;
            uint32_t bh0, bh1, bh2, bh3, bl0, bl1, bl2, bl3;
            ldsm_x4(bh0, bh1, bh2, bh3, sbase + 4 * (2 * 8704 + rowB));
            ldsm_x4(bl0, bl1, bl2, bl3, sbase + 4 * (3 * 8704 + rowB));
#pragma unroll
            for (int mt = 0; mt < 2; mt++) {
                mma_bf16(acc[mt][2 * g],     ah[mt], bh0, bh1);
                mma_bf16(acc[mt][2 * g],     ah[mt], bl0, bl1);
                mma_bf16(acc[mt][2 * g],     al[mt], bh0, bh1);
                mma_bf16(acc[mt][2 * g + 1], ah[mt], bh2, bh3);
                mma_bf16(acc[mt][2 * g + 1], ah[mt], bl2, bl3);
                mma_bf16(acc[mt][2 * g + 1], al[mt], bh2, bh3);
            }
        }
    }
    __syncthreads();                              // done reading B planes

    // ---- stage into smem planes: plane[lm][128 rows][36 (32+pad)] ----
    float* plane = (float*)sm;
#pragma unroll
    for (int nt = 0; nt < 8; nt++) {
        int c  = col0 + wn * 64 + nt * 8 + lm * 2;        // logical col (even)
        float b0 = bias[c], b1 = bias[c + 1];
        int cc = (wn * 8 + nt) * 2;
#pragma unroll
        for (int mt = 0; mt < 2; mt++) {
            int r = wm * 32 + mt * 16 + l4;
            *(float2*)(plane + lm * 4608 + r * 36 + cc)
                = make_float2(acc[mt][nt][0] + b0, acc[mt][nt][1] + b1);
            *(float2*)(plane + lm * 4608 + (r + 8) * 36 + cc)
                = make_float2(acc[mt][nt][2] + b0, acc[mt][nt][3] + b1);
        }
    }
    __syncthreads();

    // ---- coalesced writeout: 4 segments of 128B per row ----
    int d  = col0 >> 8;
    int s0 = (col0 & 128) >> 2;                   // 0 or 32
#pragma unroll
    for (int i = 0; i < 16; i++) {
        int idx = tid + i * 256;                  // 0..4095
        int p   = idx >> 10;                      // plane (lm)
        int rem = idx & 1023;
        int r   = rem >> 3, j4 = rem & 7;
        if (row0 + r < M) {
            float4 v = *(const float4*)(plane + p * 4608 + r * 36 + j4 * 4);
            *(float4*)(C + (size_t)(row0 + r) * 512 + d * 256 + p * 64 + s0 + j4 * 4) = v;
        }
    }
}

// ---------------- tensor-core BiLSTM + mean (fp16 recurrence, tanh.approx gates) --------
// 256 threads = 8 warps. Warp w: dir = w&1, mtile = w>>1. Warp owns 16 (node,dir) rows and
// computes G[16,256] = H @ Whh^T via mma.m16n8k16 fp16. Gate nonlinearity uses
// tanh.approx.f32 (1 MUFU each; sigmoid = 0.5*tanh(x/2)+0.5) -> 5 MUFU per gate-set
// instead of 10 (MUFU pipe was the binding resource). 4 q-pair groups of 8 acc tiles keep
// registers spill-free. h D-fragments repack register-only; zero intra-step syncs.
template<int L, bool GATHER>
__global__ void __launch_bounds__(256, 1)
lstm_tc(const float* __restrict__ XgA, const float* __restrict__ XgB,
        const int* __restrict__ i0, const int* __restrict__ i1,
        const int* __restrict__ i2, const int* __restrict__ i3,
        const uint32_t* __restrict__ wfA, const uint32_t* __restrict__ wfB,
        float* __restrict__ o0, float* __restrict__ o1,
        float* __restrict__ o2, float* __restrict__ o3,
        int nnodes)
{
    extern __shared__ uint32_t bsm[];            // 16384: [dir][kt][nt][lane][2] fp16
    int* idxs = (int*)(bsm + 16384);             // 64*L ints (neighbor only)

    int et = blockIdx.y;
    const float* Xg = (et & 1) ? XgB : XgA;
    const uint32_t* wfrag = (et & 1) ? wfB : wfA;
    const int* idx = (et == 0) ? i0 : (et == 1) ? i1 : (et == 2) ? i2 : i3;
    float* outp = (et == 0) ? o0 : (et == 1) ? o1 : (et == 2) ? o2 : o3;

    int tid = threadIdx.x;
#pragma unroll
    for (int i = 0; i < 16; i++)
        ((uint4*)bsm)[tid + i * 256] = ((const uint4*)wfrag)[tid + i * 256];
    if (GATHER) {
        for (int i = tid; i < 64 * L; i += 256) {
            int gix = blockIdx.x * 64 * L + i;
            idxs[i] = (gix < nnodes * L) ? idx[gix] : 0;
        }
    }
    __syncthreads();

    int lane = tid & 31, warp = tid >> 5;
    int dir = warp & 1, mtile = warp >> 1;
    int gr = lane >> 2, lm = lane & 3;
    int lrow0 = mtile * 16 + gr;                 // block-local row 0..63
    int gnode0 = blockIdx.x * 64 + lrow0;
    bool ok0 = gnode0 < nnodes;
    bool ok1 = gnode0 + 8 < nnodes;
    int cn0 = ok0 ? gnode0 : 0;
    int cn1 = ok1 ? gnode0 + 8 : 0;

    float cst[32], hsum[32];
#pragma unroll
    for (int q = 0; q < 32; q++) { cst[q] = 0.f; hsum[q] = 0.f; }
    uint32_t afr[16], nfr[16];

    const uint32_t* bd = bsm + dir * 8192;       // [kt][nt][lane][2]

#pragma unroll 1
    for (int l = 0; l < L; l++) {
        int seq = dir ? (L - 1 - l) : l;
        int xr0, xr1;
        if (GATHER) {
            xr0 = ok0 ? idxs[lrow0 * L + seq] : 0;
            xr1 = ok1 ? idxs[(lrow0 + 8) * L + seq] : 0;
        } else {
            xr0 = cn0 * L + seq;
            xr1 = cn1 * L + seq;
        }
        const float* xp0 = Xg + (size_t)xr0 * 512 + (dir << 8) + lm * 64;
        const float* xp1 = Xg + (size_t)xr1 * 512 + (dir << 8) + lm * 64;

#pragma unroll
        for (int qp = 0; qp < 4; qp++) {
            // tiles in this group: nt = s*8 + 2qp + e  (s: i/f/g/o, e: gate pair)
            float acc[8][4];
#pragma unroll
            for (int s = 0; s < 4; s++) {
                float4 v0 = *(const float4*)(xp0 + s * 16 + qp * 4);
                float4 v1 = *(const float4*)(xp1 + s * 16 + qp * 4);
                acc[s * 2][0] = v0.x; acc[s * 2][1] = v0.y;
                acc[s * 2 + 1][0] = v0.z; acc[s * 2 + 1][1] = v0.w;
                acc[s * 2][2] = v1.x; acc[s * 2][3] = v1.y;
                acc[s * 2 + 1][2] = v1.z; acc[s * 2 + 1][3] = v1.w;
            }
            if (l > 0) {
#pragma unroll
                for (int kt = 0; kt < 4; kt++) {
                    const uint32_t* bk = bd + kt * 2048 + lane * 2;
#pragma unroll
                    for (int s = 0; s < 4; s++) {
#pragma unroll
                        for (int e = 0; e < 2; e++) {
                            int nt = s * 8 + 2 * qp + e;
                            uint2 bh = *(const uint2*)(bk + nt * 64);
                            mma_f16(acc[s * 2 + e], afr + kt * 4, bh.x, bh.y);
                        }
                    }
                }
            }
            // elementwise gates for q = 2qp, 2qp+1 (lane-local) + D->A repack
#pragma unroll
            for (int e = 0; e < 2; e++) {
                int q = 2 * qp + e;
                float h[4];
#pragma unroll
                for (int j = 0; j < 4; j++) {
                    float ig = sig_fast(acc[e][j]);
                    float fg = sig_fast(acc[2 + e][j]);
                    float gg = tanh_fast(acc[4 + e][j]);
                    float og = sig_fast(acc[6 + e][j]);
                    float c = fg * cst[q * 4 + j] + ig * gg;
                    cst[q * 4 + j] = c;
                    float hv = og * tanh_fast(c);
                    hsum[q * 4 + j] += hv;
                    h[j] = hv;
                }
                int base = qp * 4 + e * 2;
                nfr[base]     = packh(h[0], h[1]);
                nfr[base + 1] = packh(h[2], h[3]);
            }
        }
        // buffer swap (register copies; old afr fully consumed this step)
#pragma unroll
        for (int i = 0; i < 16; i++) afr[i] = nfr[i];
    }

    float invL = 1.f / (float)L;
#pragma unroll
    for (int q = 0; q < 8; q++) {
        size_t col = dir * 64 + q * 8 + lm * 2;
        if (ok0)
            *(float2*)(outp + (size_t)gnode0 * 128 + col)
                = make_float2(hsum[q * 4] * invL, hsum[q * 4 + 1] * invL);
        if (ok1)
            *(float2*)(outp + (size_t)(gnode0 + 8) * 128 + col)
                = make_float2(hsum[q * 4 + 2] * invL, hsum[q * 4 + 3] * invL);
    }
}

// ---------------- attention combine: one warp per node ----------------
__global__ void __launch_bounds__(256)
combine_kernel(const float* __restrict__ c, const float* __restrict__ n1,
               const float* __restrict__ n2, const float* __restrict__ attn,
               float* __restrict__ out)
{
    int warp = threadIdx.x >> 5, lane = threadIdx.x & 31;
    int n = blockIdx.x * 8 + warp;
    size_t off = (size_t)n * 128 + lane * 4;
    float4 cv = *(const float4*)(c + off);
    float4 e1 = *(const float4*)(n1 + off);
    float4 e2 = *(const float4*)(n2 + off);
    float4 ac = *(const float4*)(attn + lane * 4);
    float4 ae = *(const float4*)(attn + 128 + lane * 4);

    float base = ac.x * cv.x + ac.y * cv.y + ac.z * cv.z + ac.w * cv.w;
    float d0   = ae.x * cv.x + ae.y * cv.y + ae.z * cv.z + ae.w * cv.w;
    float d1   = ae.x * e1.x + ae.y * e1.y + ae.z * e1.z + ae.w * e1.w;
    float d2   = ae.x * e2.x + ae.y * e2.y + ae.z * e2.z + ae.w * e2.w;
#pragma unroll
    for (int s = 16; s > 0; s >>= 1) {
        base += __shfl_xor_sync(0xffffffffu, base, s);
        d0   += __shfl_xor_sync(0xffffffffu, d0, s);
        d1   += __shfl_xor_sync(0xffffffffu, d1, s);
        d2   += __shfl_xor_sync(0xffffffffu, d2, s);
    }
    float s0 = base + d0, s1 = base + d1, s2 = base + d2;
    s0 = (s0 >= 0.f) ? s0 : 0.01f * s0;
    s1 = (s1 >= 0.f) ? s1 : 0.01f * s1;
    s2 = (s2 >= 0.f) ? s2 : 0.01f * s2;
    float mx = fmaxf(s0, fmaxf(s1, s2));
    float w0 = __expf(s0 - mx), w1 = __expf(s1 - mx), w2 = __expf(s2 - mx);
    float inv = __fdividef(1.f, w0 + w1 + w2);
    w0 *= inv; w1 *= inv; w2 *= inv;
    float4 o;
    o.x = w0 * cv.x + w1 * e1.x + w2 * e2.x;
    o.y = w0 * cv.y + w1 * e1.y + w2 * e2.y;
    o.z = w0 * cv.z + w1 * e1.z + w2 * e2.z;
    o.w = w0 * cv.w + w1 * e1.w + w2 * e2.w;
    *(float4*)(out + off) = o;
}

// ---------------- launch ----------------
extern "C" void kernel_launch(void* const* d_in, const int* in_sizes, int n_in,
                              void* d_out, int out_size)
{
    const float* feats_a = (const float*)d_in[0];
    const float* feats_b = (const float*)d_in[1];
    const float* Wih_ca  = (const float*)d_in[2];
    const float* Whh_ca  = (const float*)d_in[3];
    const float* b_ca    = (const float*)d_in[4];
    const float* Wih_cb  = (const float*)d_in[5];
    const float* Whh_cb  = (const float*)d_in[6];
    const float* b_cb    = (const float*)d_in[7];
    const float* Wih_na  = (const float*)d_in[8];
    const float* Whh_na  = (const float*)d_in[9];
    const float* b_na    = (const float*)d_in[10];
    const float* Wih_nb  = (const float*)d_in[11];
    const float* Whh_nb  = (const float*)d_in[12];
    const float* b_nb    = (const float*)d_in[13];
    const float* attn_a  = (const float*)d_in[14];
    const float* attn_b  = (const float*)d_in[15];
    const int* idx_a_a   = (const int*)d_in[16];
    const int* idx_b_a   = (const int*)d_in[17];
    const int* idx_a_b   = (const int*)d_in[18];
    const int* idx_b_b   = (const int*)d_in[19];
    float* out = (float*)d_out;

    float *xg, *Ga, *Gb, *ca, *cb, *naa, *nba, *nab, *nbb;
    uint32_t* wfrag;
    cudaGetSymbolAddress((void**)&xg,  g_xg);
    cudaGetSymbolAddress((void**)&Ga,  g_Ga);
    cudaGetSymbolAddress((void**)&Gb,  g_Gb);
    cudaGetSymbolAddress((void**)&ca,  g_ca);
    cudaGetSymbolAddress((void**)&cb,  g_cb);
    cudaGetSymbolAddress((void**)&naa, g_naa);
    cudaGetSymbolAddress((void**)&nba, g_nba);
    cudaGetSymbolAddress((void**)&nab, g_nab);
    cudaGetSymbolAddress((void**)&nbb, g_nbb);
    cudaGetSymbolAddress((void**)&wfrag, g_wfrag);

    const int gemm_smem = 4 * 128 * 68 * 4;                 // 139264
    const int lstm_c_smem = 16384 * 4 + 64 * L_CONT * 4;    // 66816
    const int lstm_n_smem = 16384 * 4 + 64 * K_FAN * 4;     // 69632
    cudaFuncSetAttribute((const void*)gemm_tc,
                         cudaFuncAttributeMaxDynamicSharedMemorySize, gemm_smem);
    cudaFuncSetAttribute((const void*)lstm_tc<L_CONT, false>,
                         cudaFuncAttributeMaxDynamicSharedMemorySize, lstm_c_smem);
    cudaFuncSetAttribute((const void*)lstm_tc<K_FAN, true>,
                         cudaFuncAttributeMaxDynamicSharedMemorySize, lstm_n_smem);

    // 0) Whh -> fp16 mma B-fragments, all four param sets
    wfrag_kernel<<<256, 256>>>(Whh_ca, Whh_cb, Whh_na, Whh_nb, wfrag);

    dim3 ggrid((30000 + 127) / 128, 4);        // M=30000 rows per GEMM launch
    const int cblk = (CCHUNK + 63) / 64;       // LSTM blocks per content chunk
    const int nblk = (N_NODES + 63) / 64;      // LSTM blocks per neighbor type

    // 1) content type a: chunked so xg stays L2-resident between GEMM and LSTM
    for (int c = 0; c < NCHUNK; c++) {
        gemm_tc<<<ggrid, 256, gemm_smem>>>(feats_a + (size_t)c * CCHUNK * L_CONT * 128,
                                           Wih_ca, b_ca, xg, CCHUNK * L_CONT);
        lstm_tc<L_CONT, false><<<cblk, 256, lstm_c_smem>>>(
            xg, xg, nullptr, nullptr, nullptr, nullptr,
            wfrag + 0 * 16384, wfrag + 0 * 16384,
            ca + (size_t)c * CCHUNK * 128, nullptr, nullptr, nullptr, CCHUNK);
    }
    // 2) content type b
    for (int c = 0; c < NCHUNK; c++) {
        gemm_tc<<<ggrid, 256, gemm_smem>>>(feats_b + (size_t)c * CCHUNK * L_CONT * 128,
                                           Wih_cb, b_cb, xg, CCHUNK * L_CONT);
        lstm_tc<L_CONT, false><<<cblk, 256, lstm_c_smem>>>(
            xg, xg, nullptr, nullptr, nullptr, nullptr,
            wfrag + 1 * 16384, wfrag + 1 * 16384,
            cb + (size_t)c * CCHUNK * 128, nullptr, nullptr, nullptr, CCHUNK);
    }

    // 3) neighbor gate tables: G_src = c_src @ Wih_n^T + b_n (gather commutes with GEMM)
    gemm_tc<<<ggrid, 256, gemm_smem>>>(ca, Wih_na, b_na, Ga, N_NODES);
    gemm_tc<<<ggrid, 256, gemm_smem>>>(cb, Wih_nb, b_nb, Gb, N_NODES);

    // 4) all four neighbor BiLSTMs in ONE fused launch (blockIdx.y = edge type)
    lstm_tc<K_FAN, true><<<dim3(nblk, 4), 256, lstm_n_smem>>>(
        Ga, Gb, idx_a_a, idx_b_a, idx_a_b, idx_b_b,
        wfrag + 2 * 16384, wfrag + 3 * 16384,
        naa, nba, nab, nbb, N_NODES);

    // 5) attention combine -> out[2, N, 128]
    combine_kernel<<<N_NODES / 8, 256>>>(ca, naa, nba, attn_a, out);
    combine_kernel<<<N_NODES / 8, 256>>>(cb, nab, nbb, attn_b, out + (size_t)N_NODES * 128);
}

// round 15
// speedup vs baseline: 2.2295x; 1.0688x over previous
#include <cuda_runtime.h>
#include <cuda_bf16.h>
#include <cuda_fp16.h>
#include <cstdint>

#define N_NODES 30000
#define L_CONT  5
#define K_FAN   16
#define CCHUNK  6000          // content chunk (fp16 xg chunk = 30.7 MB -> L2 resident)
#define NCHUNK  5

// ---------------- device scratch (static: no allocations allowed) ----------------
__device__ __half   g_xg [CCHUNK * L_CONT * 512]; // content input-gate chunk (permuted+bias, fp16)
__device__ __half   g_Ga [N_NODES * 512];         // neighbor gate table, src a (fp16: both fit L2)
__device__ __half   g_Gb [N_NODES * 512];         // neighbor gate table, src b
__device__ float    g_ca [N_NODES * 128];
__device__ float    g_cb [N_NODES * 128];
__device__ float    g_naa[N_NODES * 128];
__device__ float    g_nba[N_NODES * 128];
__device__ float    g_nab[N_NODES * 128];
__device__ float    g_nbb[N_NODES * 128];
__device__ uint32_t g_wfrag[4 * 16384];           // fp16 Whh B-fragments: [p][dir][kt][nt][lane][2]

// ---------------- helpers ----------------
__device__ __forceinline__ float tanh_fast(float x) {
    float y; asm("tanh.approx.f32 %0, %1;" : "=f"(y) : "f"(x)); return y;
}
__device__ __forceinline__ float sig_fast(float x) {
    return fmaf(0.5f, tanh_fast(0.5f * x), 0.5f);   // sigmoid via single MUFU tanh
}
__device__ __forceinline__ uint32_t packbf(__nv_bfloat16 a, __nv_bfloat16 b) {
    __nv_bfloat162 v; v.x = a; v.y = b;
    return *(uint32_t*)&v;
}
__device__ __forceinline__ uint32_t packh(float a, float b) {
    __half2 v = __floats2half2_rn(a, b);
    return *(uint32_t*)&v;
}
__device__ __forceinline__ void split2(float x, float y, uint32_t& hi, uint32_t& lo) {
    __nv_bfloat16 hx = __float2bfloat16(x);
    __nv_bfloat16 hy = __float2bfloat16(y);
    hi = packbf(hx, hy);
    lo = packbf(__float2bfloat16(x - __bfloat162float(hx)),
                __float2bfloat16(y - __bfloat162float(hy)));
}
__device__ __forceinline__ void mma_bf16(float* d, const uint32_t* a, uint32_t b0, uint32_t b1) {
    asm volatile(
        "mma.sync.aligned.m16n8k16.row.col.f32.bf16.bf16.f32 "
        "{%0,%1,%2,%3}, {%4,%5,%6,%7}, {%8,%9}, {%0,%1,%2,%3};\n"
        : "+f"(d[0]), "+f"(d[1]), "+f"(d[2]), "+f"(d[3])
        : "r"(a[0]), "r"(a[1]), "r"(a[2]), "r"(a[3]), "r"(b0), "r"(b1));
}
__device__ __forceinline__ void mma_f16(float* d, const uint32_t* a, uint32_t b0, uint32_t b1) {
    asm volatile(
        "mma.sync.aligned.m16n8k16.row.col.f32.f16.f16.f32 "
        "{%0,%1,%2,%3}, {%4,%5,%6,%7}, {%8,%9}, {%0,%1,%2,%3};\n"
        : "+f"(d[0]), "+f"(d[1]), "+f"(d[2]), "+f"(d[3])
        : "r"(a[0]), "r"(a[1]), "r"(a[2]), "r"(a[3]), "r"(b0), "r"(b1));
}
__device__ __forceinline__ void ldsm_x4(uint32_t& r0, uint32_t& r1, uint32_t& r2, uint32_t& r3,
                                        uint32_t addr) {
    asm volatile("ldmatrix.sync.aligned.m8n8.x4.shared.b16 {%0,%1,%2,%3}, [%4];"
                 : "=r"(r0), "=r"(r1), "=r"(r2), "=r"(r3) : "r"(addr));
}

// -------- Whh -> fp16 B-fragment swizzle, exact mma.m16n8k16 B layout --------
// out[p][dir][kt][nt][lane][j]: n = nt*8 + (lane>>2), k = kt*16 + (lane&3)*2 + j*8
__global__ void wfrag_kernel(const float* __restrict__ w0, const float* __restrict__ w1,
                             const float* __restrict__ w2, const float* __restrict__ w3,
                             uint32_t* __restrict__ out)
{
    int i = blockIdx.x * 256 + threadIdx.x;          // 65536 total
    int j    = i & 1;
    int lane = (i >> 1) & 31;
    int nt   = (i >> 6) & 31;
    int kt   = (i >> 11) & 3;
    int dir  = (i >> 13) & 1;
    int p    = i >> 14;
    const float* w = (p == 0) ? w0 : (p == 1) ? w1 : (p == 2) ? w2 : w3;
    int n = nt * 8 + (lane >> 2);
    int k = kt * 16 + (lane & 3) * 2 + j * 8;
    out[i] = packh(w[dir * 16384 + n * 64 + k], w[dir * 16384 + n * 64 + k + 1]);
}

// ---------------- tensor-core GEMM: C[M,512] = A[M,128] * W[512,128]^T + bias (fp16 out) --
// bf16x3 split, fp32 accumulate, fp16 output in the permuted gate layout.
__global__ void __launch_bounds__(256, 1)
gemm_tc(const float* __restrict__ A, const float* __restrict__ W,
        const float* __restrict__ bias, __half* __restrict__ C, int M)
{
    extern __shared__ uint32_t sm[];
    uint32_t* Ahi = sm;
    uint32_t* Alo = sm + 128 * 68;
    uint32_t* Whi = sm + 2 * 128 * 68;
    uint32_t* Wlo = sm + 3 * 128 * 68;

    int tid  = threadIdx.x;
    int row0 = blockIdx.x * 128;
    int col0 = blockIdx.y * 128;

#pragma unroll
    for (int i = 0; i < 16; i++) {
        int t = tid + i * 256;
        int r = t >> 5, j = t & 31;
        float4 v = make_float4(0.f, 0.f, 0.f, 0.f);
        if (row0 + r < M) v = *(const float4*)(A + (size_t)(row0 + r) * 128 + j * 4);
        uint32_t h0, l0, h1, l1;
        split2(v.x, v.y, h0, l0);
        split2(v.z, v.w, h1, l1);
        Ahi[r * 68 + j * 2]     = h0;
        Ahi[r * 68 + j * 2 + 1] = h1;
        Alo[r * 68 + j * 2]     = l0;
        Alo[r * 68 + j * 2 + 1] = l1;
    }
#pragma unroll
    for (int i = 0; i < 16; i++) {
        int t = tid + i * 256;
        int r = t >> 5, j = t & 31;
        float4 v = *(const float4*)(W + (size_t)(col0 + r) * 128 + j * 4);
        uint32_t h0, l0, h1, l1;
        split2(v.x, v.y, h0, l0);
        split2(v.z, v.w, h1, l1);
        Whi[r * 68 + j * 2]     = h0;
        Whi[r * 68 + j * 2 + 1] = h1;
        Wlo[r * 68 + j * 2]     = l0;
        Wlo[r * 68 + j * 2 + 1] = l1;
    }
    __syncthreads();

    int lane = tid & 31, warp = tid >> 5;
    int wm = warp >> 1, wn = warp & 1;
    int l4 = lane >> 2, lm = lane & 3;

    uint32_t sbase = (uint32_t)__cvta_generic_to_shared(sm);
    int rA = (lane & 7) + ((lane >> 3) & 1) * 8;
    int kA = ((lane >> 4) & 1) * 4;
    int rB = (lane & 7) + ((lane >> 4) & 1) * 8;
    int kB = ((lane >> 3) & 1) * 4;

    float acc[2][8][4];
#pragma unroll
    for (int mt = 0; mt < 2; mt++)
#pragma unroll
        for (int nt = 0; nt < 8; nt++)
#pragma unroll
            for (int q = 0; q < 4; q++) acc[mt][nt][q] = 0.f;

#pragma unroll
    for (int ks = 0; ks < 8; ks++) {
        uint32_t ah[2][4], al[2][4];
#pragma unroll
        for (int mt = 0; mt < 2; mt++) {
            uint32_t rowA = (wm * 32 + mt * 16 + rA) * 68 + ks * 8 + kA;
            ldsm_x4(ah[mt][0], ah[mt][1], ah[mt][2], ah[mt][3], sbase + 4 * rowA);
            ldsm_x4(al[mt][0], al[mt][1], al[mt][2], al[mt][3],
                    sbase + 4 * (8704 + rowA));
        }
#pragma unroll
        for (int g = 0; g < 4; g++) {
            uint32_t rowB = (wn * 64 + g * 16 + rB) * 68 + ks * 8 + kB;
            uint32_t bh0, bh1, bh2, bh3, bl0, bl1, bl2, bl3;
            ldsm_x4(bh0, bh1, bh2, bh3, sbase + 4 * (2 * 8704 + rowB));
            ldsm_x4(bl0, bl1, bl2, bl3, sbase + 4 * (3 * 8704 + rowB));
#pragma unroll
            for (int mt = 0; mt < 2; mt++) {
                mma_bf16(acc[mt][2 * g],     ah[mt], bh0, bh1);
                mma_bf16(acc[mt][2 * g],     ah[mt], bl0, bl1);
                mma_bf16(acc[mt][2 * g],     al[mt], bh0, bh1);
                mma_bf16(acc[mt][2 * g + 1], ah[mt], bh2, bh3);
                mma_bf16(acc[mt][2 * g + 1], ah[mt], bl2, bl3);
                mma_bf16(acc[mt][2 * g + 1], al[mt], bh2, bh3);
            }
        }
    }
    __syncthreads();                              // done reading B planes

    // ---- stage fp16 into smem planes: plane[lm] = 128 rows x 16 words (stride 20) ----
#pragma unroll
    for (int nt = 0; nt < 8; nt++) {
        int c  = col0 + wn * 64 + nt * 8 + lm * 2;        // logical col (even)
        float b0 = bias[c], b1 = bias[c + 1];
        int cc2 = wn * 8 + nt;                            // word index in row (0..15)
#pragma unroll
        for (int mt = 0; mt < 2; mt++) {
            int r = wm * 32 + mt * 16 + l4;
            sm[lm * 2568 + r * 20 + cc2]       = packh(acc[mt][nt][0] + b0, acc[mt][nt][1] + b1);
            sm[lm * 2568 + (r + 8) * 20 + cc2] = packh(acc[mt][nt][2] + b0, acc[mt][nt][3] + b1);
        }
    }
    __syncthreads();

    // ---- coalesced fp16 writeout: uint4 = 8 halfs per store ----
    int d  = col0 >> 8;
    int s0 = (col0 & 128) >> 2;                   // 0 or 32 (element index within 512-row)
#pragma unroll
    for (int i = 0; i < 8; i++) {
        int u   = tid + i * 256;                  // uint4 index 0..2047
        int p   = u >> 9;                         // plane
        int rem = u & 511;
        int r   = rem >> 2, j4 = (rem & 3) * 4;   // word offset in row
        if (row0 + r < M) {
            uint4 v = *(uint4*)&sm[p * 2568 + r * 20 + j4];
            *(uint4*)(C + (size_t)(row0 + r) * 512 + d * 256 + p * 64 + s0 + 2 * j4) = v;
        }
    }
}

// ---------------- tensor-core BiLSTM + mean (fp16 recurrence + fp16 gate tables) ---------
// 256 threads = 8 warps. Warp w: dir = w&1, mtile = w>>1; warp owns 16 (node,dir) rows.
// G[16,256] = H @ Whh^T via mma.m16n8k16 fp16, acc zero-init; the gathered fp16 xg rows
// are loaded at step start (uint2 = 4 halfs) and added at GATE time, so the MMA block
// never waits on the gather. tanh.approx gates; h D-fragments repack register-only.
template<int L, bool GATHER>
__global__ void __launch_bounds__(256, 1)
lstm_tc(const __half* __restrict__ XgA, const __half* __restrict__ XgB,
        const int* __restrict__ i0, const int* __restrict__ i1,
        const int* __restrict__ i2, const int* __restrict__ i3,
        const uint32_t* __restrict__ wfA, const uint32_t* __restrict__ wfB,
        float* __restrict__ o0, float* __restrict__ o1,
        float* __restrict__ o2, float* __restrict__ o3,
        int nnodes)
{
    extern __shared__ uint32_t bsm[];            // 16384: [dir][kt][nt][lane][2] fp16
    int* idxs = (int*)(bsm + 16384);             // 64*L ints (neighbor only)

    int et = blockIdx.y;
    const __half* Xg = (et & 1) ? XgB : XgA;
    const uint32_t* wfrag = (et & 1) ? wfB : wfA;
    const int* idx = (et == 0) ? i0 : (et == 1) ? i1 : (et == 2) ? i2 : i3;
    float* outp = (et == 0) ? o0 : (et == 1) ? o1 : (et == 2) ? o2 : o3;

    int tid = threadIdx.x;
#pragma unroll
    for (int i = 0; i < 16; i++)
        ((uint4*)bsm)[tid + i * 256] = ((const uint4*)wfrag)[tid + i * 256];
    if (GATHER) {
        for (int i = tid; i < 64 * L; i += 256) {
            int gix = blockIdx.x * 64 * L + i;
            idxs[i] = (gix < nnodes * L) ? idx[gix] : 0;
        }
    }
    __syncthreads();

    int lane = tid & 31, warp = tid >> 5;
    int dir = warp & 1, mtile = warp >> 1;
    int gr = lane >> 2, lm = lane & 3;
    int lrow0 = mtile * 16 + gr;                 // block-local row 0..63
    int gnode0 = blockIdx.x * 64 + lrow0;
    bool ok0 = gnode0 < nnodes;
    bool ok1 = gnode0 + 8 < nnodes;
    int cn0 = ok0 ? gnode0 : 0;
    int cn1 = ok1 ? gnode0 + 8 : 0;

    float cst[32], hsum[32];
#pragma unroll
    for (int q = 0; q < 32; q++) { cst[q] = 0.f; hsum[q] = 0.f; }
    uint32_t afr[16], nfr[16];

    const uint32_t* bd = bsm + dir * 8192;       // [kt][nt][lane][2]

#pragma unroll 1
    for (int l = 0; l < L; l++) {
        int seq = dir ? (L - 1 - l) : l;
        int xr0, xr1;
        if (GATHER) {
            xr0 = ok0 ? idxs[lrow0 * L + seq] : 0;
            xr1 = ok1 ? idxs[(lrow0 + 8) * L + seq] : 0;
        } else {
            xr0 = cn0 * L + seq;
            xr1 = cn1 * L + seq;
        }
        const __half* hp0 = Xg + (size_t)xr0 * 512 + (dir << 8) + lm * 64;
        const __half* hp1 = Xg + (size_t)xr1 * 512 + (dir << 8) + lm * 64;

#pragma unroll
        for (int qp = 0; qp < 4; qp++) {
            // xg loads for this q-pair group: 4 halfs per (s,row) = uint2 (8B)
            uint2 x0[4], x1[4];
#pragma unroll
            for (int s = 0; s < 4; s++) {
                x0[s] = *(const uint2*)(hp0 + s * 16 + qp * 4);
                x1[s] = *(const uint2*)(hp1 + s * 16 + qp * 4);
            }
            // recurrence MMAs (do not depend on the loads above)
            float acc[8][4];
#pragma unroll
            for (int t8 = 0; t8 < 8; t8++)
#pragma unroll
                for (int q4 = 0; q4 < 4; q4++) acc[t8][q4] = 0.f;
            if (l > 0) {
#pragma unroll
                for (int kt = 0; kt < 4; kt++) {
                    const uint32_t* bk = bd + kt * 2048 + lane * 2;
#pragma unroll
                    for (int s = 0; s < 4; s++) {
#pragma unroll
                        for (int e = 0; e < 2; e++) {
                            int nt = s * 8 + 2 * qp + e;
                            uint2 bh = *(const uint2*)(bk + nt * 64);
                            mma_f16(acc[s * 2 + e], afr + kt * 4, bh.x, bh.y);
                        }
                    }
                }
            }
            // gates: add fp16 xg at gate time, lane-local, then D->A repack
#pragma unroll
            for (int e = 0; e < 2; e++) {
                int q = 2 * qp + e;
                float xf[4][4];                  // [s][j]
#pragma unroll
                for (int s = 0; s < 4; s++) {
                    uint32_t w0 = e ? x0[s].y : x0[s].x;
                    uint32_t w1 = e ? x1[s].y : x1[s].x;
                    float2 f0 = __half22float2(*(__half2*)&w0);
                    float2 f1 = __half22float2(*(__half2*)&w1);
                    xf[s][0] = f0.x; xf[s][1] = f0.y;
                    xf[s][2] = f1.x; xf[s][3] = f1.y;
                }
                float h[4];
#pragma unroll
                for (int j = 0; j < 4; j++) {
                    float ig = sig_fast(acc[e][j]     + xf[0][j]);
                    float fg = sig_fast(acc[2 + e][j] + xf[1][j]);
                    float gg = tanh_fast(acc[4 + e][j] + xf[2][j]);
                    float og = sig_fast(acc[6 + e][j] + xf[3][j]);
                    float c = fg * cst[q * 4 + j] + ig * gg;
                    cst[q * 4 + j] = c;
                    float hv = og * tanh_fast(c);
                    hsum[q * 4 + j] += hv;
                    h[j] = hv;
                }
                int base = qp * 4 + e * 2;
                nfr[base]     = packh(h[0], h[1]);
                nfr[base + 1] = packh(h[2], h[3]);
            }
        }
        // buffer swap (register copies; old afr fully consumed this step)
#pragma unroll
        for (int i = 0; i < 16; i++) afr[i] = nfr[i];
    }

    float invL = 1.f / (float)L;
#pragma unroll
    for (int q = 0; q < 8; q++) {
        size_t col = dir * 64 + q * 8 + lm * 2;
        if (ok0)
            *(float2*)(outp + (size_t)gnode0 * 128 + col)
                = make_float2(hsum[q * 4] * invL, hsum[q * 4 + 1] * invL);
        if (ok1)
            *(float2*)(outp + (size_t)(gnode0 + 8) * 128 + col)
                = make_float2(hsum[q * 4 + 2] * invL, hsum[q * 4 + 3] * invL);
    }
}

// ---------------- attention combine: one warp per node ----------------
__global__ void __launch_bounds__(256)
combine_kernel(const float* __restrict__ c, const float* __restrict__ n1,
               const float* __restrict__ n2, const float* __restrict__ attn,
               float* __restrict__ out)
{
    int warp = threadIdx.x >> 5, lane = threadIdx.x & 31;
    int n = blockIdx.x * 8 + warp;
    size_t off = (size_t)n * 128 + lane * 4;
    float4 cv = *(const float4*)(c + off);
    float4 e1 = *(const float4*)(n1 + off);
    float4 e2 = *(const float4*)(n2 + off);
    float4 ac = *(const float4*)(attn + lane * 4);
    float4 ae = *(const float4*)(attn + 128 + lane * 4);

    float base = ac.x * cv.x + ac.y * cv.y + ac.z * cv.z + ac.w * cv.w;
    float d0   = ae.x * cv.x + ae.y * cv.y + ae.z * cv.z + ae.w * cv.w;
    float d1   = ae.x * e1.x + ae.y * e1.y + ae.z * e1.z + ae.w * e1.w;
    float d2   = ae.x * e2.x + ae.y * e2.y + ae.z * e2.z + ae.w * e2.w;
#pragma unroll
    for (int s = 16; s > 0; s >>= 1) {
        base += __shfl_xor_sync(0xffffffffu, base, s);
        d0   += __shfl_xor_sync(0xffffffffu, d0, s);
        d1   += __shfl_xor_sync(0xffffffffu, d1, s);
        d2   += __shfl_xor_sync(0xffffffffu, d2, s);
    }
    float s0 = base + d0, s1 = base + d1, s2 = base + d2;
    s0 = (s0 >= 0.f) ? s0 : 0.01f * s0;
    s1 = (s1 >= 0.f) ? s1 : 0.01f * s1;
    s2 = (s2 >= 0.f) ? s2 : 0.01f * s2;
    float mx = fmaxf(s0, fmaxf(s1, s2));
    float w0 = __expf(s0 - mx), w1 = __expf(s1 - mx), w2 = __expf(s2 - mx);
    float inv = __fdividef(1.f, w0 + w1 + w2);
    w0 *= inv; w1 *= inv; w2 *= inv;
    float4 o;
    o.x = w0 * cv.x + w1 * e1.x + w2 * e2.x;
    o.y = w0 * cv.y + w1 * e1.y + w2 * e2.y;
    o.z = w0 * cv.z + w1 * e1.z + w2 * e2.z;
    o.w = w0 * cv.w + w1 * e1.w + w2 * e2.w;
    *(float4*)(out + off) = o;
}

// ---------------- launch ----------------
extern "C" void kernel_launch(void* const* d_in, const int* in_sizes, int n_in,
                              void* d_out, int out_size)
{
    const float* feats_a = (const float*)d_in[0];
    const float* feats_b = (const float*)d_in[1];
    const float* Wih_ca  = (const float*)d_in[2];
    const float* Whh_ca  = (const float*)d_in[3];
    const float* b_ca    = (const float*)d_in[4];
    const float* Wih_cb  = (const float*)d_in[5];
    const float* Whh_cb  = (const float*)d_in[6];
    const float* b_cb    = (const float*)d_in[7];
    const float* Wih_na  = (const float*)d_in[8];
    const float* Whh_na  = (const float*)d_in[9];
    const float* b_na    = (const float*)d_in[10];
    const float* Wih_nb  = (const float*)d_in[11];
    const float* Whh_nb  = (const float*)d_in[12];
    const float* b_nb    = (const float*)d_in[13];
    const float* attn_a  = (const float*)d_in[14];
    const float* attn_b  = (const float*)d_in[15];
    const int* idx_a_a   = (const int*)d_in[16];
    const int* idx_b_a   = (const int*)d_in[17];
    const int* idx_a_b   = (const int*)d_in[18];
    const int* idx_b_b   = (const int*)d_in[19];
    float* out = (float*)d_out;

    __half *xg, *Ga, *Gb;
    float *ca, *cb, *naa, *nba, *nab, *nbb;
    uint32_t* wfrag;
    cudaGetSymbolAddress((void**)&xg,  g_xg);
    cudaGetSymbolAddress((void**)&Ga,  g_Ga);
    cudaGetSymbolAddress((void**)&Gb,  g_Gb);
    cudaGetSymbolAddress((void**)&ca,  g_ca);
    cudaGetSymbolAddress((void**)&cb,  g_cb);
    cudaGetSymbolAddress((void**)&naa, g_naa);
    cudaGetSymbolAddress((void**)&nba, g_nba);
    cudaGetSymbolAddress((void**)&nab, g_nab);
    cudaGetSymbolAddress((void**)&nbb, g_nbb);
    cudaGetSymbolAddress((void**)&wfrag, g_wfrag);

    const int gemm_smem = 4 * 128 * 68 * 4;                 // 139264
    const int lstm_c_smem = 16384 * 4 + 64 * L_CONT * 4;    // 66816
    const int lstm_n_smem = 16384 * 4 + 64 * K_FAN * 4;     // 69632
    cudaFuncSetAttribute((const void*)gemm_tc,
                         cudaFuncAttributeMaxDynamicSharedMemorySize, gemm_smem);
    cudaFuncSetAttribute((const void*)lstm_tc<L_CONT, false>,
                         cudaFuncAttributeMaxDynamicSharedMemorySize, lstm_c_smem);
    cudaFuncSetAttribute((const void*)lstm_tc<K_FAN, true>,
                         cudaFuncAttributeMaxDynamicSharedMemorySize, lstm_n_smem);

    // 0) Whh -> fp16 mma B-fragments, all four param sets
    wfrag_kernel<<<256, 256>>>(Whh_ca, Whh_cb, Whh_na, Whh_nb, wfrag);

    dim3 ggrid((30000 + 127) / 128, 4);        // M=30000 rows per GEMM launch
    const int cblk = (CCHUNK + 63) / 64;       // LSTM blocks per content chunk
    const int nblk = (N_NODES + 63) / 64;      // LSTM blocks per neighbor type

    // 1) content type a: chunked so fp16 xg stays L2-resident between GEMM and LSTM
    for (int c = 0; c < NCHUNK; c++) {
        gemm_tc<<<ggrid, 256, gemm_smem>>>(feats_a + (size_t)c * CCHUNK * L_CONT * 128,
                                           Wih_ca, b_ca, xg, CCHUNK * L_CONT);
        lstm_tc<L_CONT, false><<<cblk, 256, lstm_c_smem>>>(
            xg, xg, nullptr, nullptr, nullptr, nullptr,
            wfrag + 0 * 16384, wfrag + 0 * 16384,
            ca + (size_t)c * CCHUNK * 128, nullptr, nullptr, nullptr, CCHUNK);
    }
    // 2) content type b
    for (int c = 0; c < NCHUNK; c++) {
        gemm_tc<<<ggrid, 256, gemm_smem>>>(feats_b + (size_t)c * CCHUNK * L_CONT * 128,
                                           Wih_cb, b_cb, xg, CCHUNK * L_CONT);
        lstm_tc<L_CONT, false><<<cblk, 256, lstm_c_smem>>>(
            xg, xg, nullptr, nullptr, nullptr, nullptr,
            wfrag + 1 * 16384, wfrag + 1 * 16384,
            cb + (size_t)c * CCHUNK * 128, nullptr, nullptr, nullptr, CCHUNK);
    }

    // 3) neighbor gate tables (fp16: Ga+Gb = 61 MB, L2-resident): G = c @ Wih_n^T + b_n
    gemm_tc<<<ggrid, 256, gemm_smem>>>(ca, Wih_na, b_na, Ga, N_NODES);
    gemm_tc<<<ggrid, 256, gemm_smem>>>(cb, Wih_nb, b_nb, Gb, N_NODES);

    // 4) all four neighbor BiLSTMs in ONE fused launch (blockIdx.y = edge type)
    lstm_tc<K_FAN, true><<<dim3(nblk, 4), 256, lstm_n_smem>>>(
        Ga, Gb, idx_a_a, idx_b_a, idx_a_b, idx_b_b,
        wfrag + 2 * 16384, wfrag + 3 * 16384,
        naa, nba, nab, nbb, N_NODES);

    // 5) attention combine -> out[2, N, 128]
    combine_kernel<<<N_NODES / 8, 256>>>(ca, naa, nba, attn_a, out);
    combine_kernel<<<N_NODES / 8, 256>>>(cb, nab, nbb, attn_b, out + (size_t)N_NODES * 128);
}